// round 11
// baseline (speedup 1.0000x reference)
#include <cuda_runtime.h>
#include <cuda_bf16.h>
#include <math.h>
#include <stdint.h>

// Problem constants
#define BATCH 8
#define SEQ   4096
#define PP    400           // 20x20
#define NSAMP (BATCH*SEQ)   // 32768
#define ITERS 14
#define NBLK  256           // persistent selection grid

// GEMM: M=32768 (64/CTA), N=448 (56 n8-tiles, 7 per warp), K=400 (25 k16-steps)
#define NK16  25
#define NNT   56

typedef unsigned long long u64;

// ---------------- scratch (static __device__, no allocations) ----------------
__device__ unsigned g_Bfrag[NK16 * NNT * 2 * 64];  // [k16][nt][plane][lane][2] u32
__device__ float  g_m[NSAMP];
__device__ float  g_keff[25];
__device__ float  g_c;
__device__ float  g_act[BATCH * PP];
__device__ int    g_sel[BATCH * PP];
__device__ int    g_done[BATCH];
__device__ int    g_pid[BATCH];
__device__ float  g_part[BATCH * 32];
__device__ float  g_res[BATCH * SEQ];
__device__ float  g_v2[BATCH * SEQ];
__device__ unsigned g_bar;

// ---------------- helpers ----------------
__device__ __forceinline__ void bsplit(float lo, float hi, uint32_t& h, uint32_t& l)
{
    asm("cvt.rn.bf16x2.f32 %0,%1,%2;" : "=r"(h) : "f"(hi), "f"(lo));
    float hlo = __uint_as_float(h << 16);
    float hhi = __uint_as_float(h & 0xffff0000u);
    asm("cvt.rn.bf16x2.f32 %0,%1,%2;" : "=r"(l) : "f"(hi - hhi), "f"(lo - hlo));
}
__device__ __forceinline__ void mma16816(float* c, const uint32_t* a,
                                         uint32_t b0, uint32_t b1)
{
    asm volatile(
        "mma.sync.aligned.m16n8k16.row.col.f32.bf16.bf16.f32 "
        "{%0,%1,%2,%3},{%4,%5,%6,%7},{%8,%9},{%0,%1,%2,%3};"
        : "+f"(c[0]), "+f"(c[1]), "+f"(c[2]), "+f"(c[3])
        : "r"(a[0]), "r"(a[1]), "r"(a[2]), "r"(a[3]), "r"(b0), "r"(b1));
}

// ---------------- prep: B fragment planes + conv compose + barrier reset -----
__global__ void prep_kernel(const float* __restrict__ fc2_w,
                            const float* __restrict__ c1w, const float* __restrict__ c1b,
                            const float* __restrict__ c2w, const float* __restrict__ c2b)
{
    if (blockIdx.x < 700) {
        int e = blockIdx.x * 256 + threadIdx.x;   // [k16][nt][plane][lane][reg]
        int reg   = e & 1;
        int lane  = (e >> 1) & 31;
        int plane = (e >> 6) & 1;
        int r     = e >> 7;                        // 0..1399
        int nt  = r % NNT;
        int k16 = r / NNT;
        int g = lane >> 2, tg = lane & 3;
        int n  = nt * 8 + g;
        int kr = k16 * 16 + tg * 2 + reg * 8;
        float v0 = (n < PP) ? fc2_w[n * PP + kr] : 0.f;
        float v1 = (n < PP) ? fc2_w[n * PP + kr + 1] : 0.f;
        uint32_t h, l;
        bsplit(v0, v1, h, l);
        g_Bfrag[(((size_t)r * 2 + plane) * 32 + lane) * 2 + reg] = plane ? l : h;
        return;
    }
    // last block: keff compose + g_bar reset
    __shared__ float s1w[45], s1b[5], s2w[450], s2b[10], part[250];
    int t = threadIdx.x;
    if (t == 0) g_bar = 0u;
    if (t < 45)  s1w[t] = c1w[t];
    if (t < 5)   s1b[t] = c1b[t];
    for (int i = t; i < 450; i += 256) s2w[i] = c2w[i];
    if (t < 10)  s2b[t] = c2b[t];
    __syncthreads();
    if (t < 250) {
        int uv = t / 10, oc = t % 10;
        int u = uv / 5, v = uv % 5;
        float acc = 0.f;
        for (int ic = 0; ic < 5; ++ic)
#pragma unroll
            for (int ay = 0; ay < 3; ++ay) {
                int by = u - ay; if (by < 0 || by > 2) continue;
#pragma unroll
                for (int ax = 0; ax < 3; ++ax) {
                    int bx = v - ax; if (bx < 0 || bx > 2) continue;
                    acc += s2w[((oc * 5 + ic) * 3 + by) * 3 + bx] * s1w[(ic * 3 + ay) * 3 + ax];
                }
            }
        part[t] = acc;
    }
    __syncthreads();
    if (t < 25) {
        float acc = 0.f;
#pragma unroll
        for (int oc = 0; oc < 10; ++oc) acc += part[t * 10 + oc];
        g_keff[t] = acc * 0.1f;
    } else if (t == 25) {
        float acc = 0.f;
        for (int oc = 0; oc < 10; ++oc) {
            float t2 = s2b[oc];
            for (int ic = 0; ic < 5; ++ic) {
                float sw = 0.f;
#pragma unroll
                for (int bb = 0; bb < 9; ++bb) sw += s2w[(oc * 5 + ic) * 9 + bb];
                t2 += s1b[ic] * sw;
            }
            acc += t2;
        }
        g_c = acc * 0.1f;
    }
}

// ---- kernel B: fc1+ln1 + mma.sync bf16-split GEMM + ln2 + conv + 0.1*sigmoid
#define BM 64
#define AH_STRIDE 404
#define REGION (BM * AH_STRIDE)        // fp32 h1 tile, later reused as Cs
#define P_FW   (REGION)                // 1200
#define P_FB   (P_FW + 1200)
#define P_L1G  (P_FB + PP)
#define P_L1B  (P_L1G + PP)
#define P_PB   (P_L1B + PP)
#define P_PG   (P_PB + PP)
#define P_PB2  (P_PG + PP)
#define P_KS   (P_PB2 + PP)            // 26
#define SMEM_TOTAL ((P_KS + 32) * 4)

__global__ void __launch_bounds__(256, 1) kernelB(
    const float* __restrict__ x0,
    const float* __restrict__ fc1_w, const float* __restrict__ fc1_b,
    const float* __restrict__ ln1_g, const float* __restrict__ ln1_b,
    const float* __restrict__ fc2_b, const float* __restrict__ ln2_g,
    const float* __restrict__ ln2_b, float* __restrict__ out)
{
    extern __shared__ float smf[];
    float* Ah = smf;                   // [64][404], fp32; overlaid by Cs later

    int tid = threadIdx.x, lane = tid & 31, wid = tid >> 5;
    int s0 = blockIdx.x * BM;

    for (int i = tid; i < 1200; i += 256) smf[P_FW + i] = fc1_w[i];
    for (int i = tid; i < PP; i += 256) {
        smf[P_FB + i] = fc1_b[i]; smf[P_L1G + i] = ln1_g[i]; smf[P_L1B + i] = ln1_b[i];
        smf[P_PB + i] = fc2_b[i]; smf[P_PG + i] = ln2_g[i]; smf[P_PB2 + i] = ln2_b[i];
    }
    if (tid < 26) smf[P_KS + tid] = (tid < 25) ? g_keff[tid] : g_c;
    __syncthreads();

    // ---- fused fc1 + relu + ln1 into Ah (one warp per sample, 8 rounds) ----
    for (int r = wid; r < BM; r += 8) {
        int ss = s0 + r;
        const float* xp = x0 + (size_t)ss * 3;
        float xa = xp[0], xb = xp[1], xc = xp[2];
        if (lane == 0) g_m[ss] = (xa + xb + xc) * (1.f / 3.f);
        float v[13];
        float sum = 0.f, sq = 0.f;
#pragma unroll
        for (int k = 0; k < 13; ++k) {
            int q = lane + 32 * k;
            float h = 0.f;
            if (q < PP) {
                h = fmaxf(xa * smf[P_FW + q * 3] + xb * smf[P_FW + q * 3 + 1]
                        + xc * smf[P_FW + q * 3 + 2] + smf[P_FB + q], 0.f);
            }
            v[k] = h; sum += h; sq += h * h;
        }
        for (int o = 16; o; o >>= 1) {
            sum += __shfl_xor_sync(~0u, sum, o);
            sq  += __shfl_xor_sync(~0u, sq, o);
        }
        float mu = sum * (1.f / PP);
        float var = sq * (1.f / PP) - mu * mu;
        float rs = rsqrtf(var + 1e-5f);
#pragma unroll
        for (int k = 0; k < 13; ++k) {
            int q = lane + 32 * k;
            if (q < PP) Ah[r * AH_STRIDE + q] = (v[k] - mu) * rs * smf[P_L1G + q] + smf[P_L1B + q];
        }
    }
    __syncthreads();

    // ---- mma.sync bf16-split mainloop ----
    // Each warp: ALL 4 m16-blocks x 7 n8-tiles (nt = wid*7+j).
    int g = lane >> 2, tg = lane & 3;
    float acc[4][7][4];
#pragma unroll
    for (int mb = 0; mb < 4; ++mb)
#pragma unroll
        for (int j = 0; j < 7; ++j)
#pragma unroll
            for (int i = 0; i < 4; ++i) acc[mb][j][i] = 0.f;

    const u64* bfr = (const u64*)g_Bfrag;

    for (int k16 = 0; k16 < NK16; ++k16) {
        // hoisted B loads: issue all 14 LDG first, A-split work covers latency
        size_t base = ((size_t)(k16 * NNT + wid * 7)) * 64 + lane;
        u64 w0[7], w1[7];
#pragma unroll
        for (int j = 0; j < 7; ++j) {
            w0[j] = bfr[base + (size_t)j * 64];
            w1[j] = bfr[base + (size_t)j * 64 + 32];
        }

        int kb = k16 * 16;
        uint32_t aH[4][4], aL[4][4];
#pragma unroll
        for (int mb = 0; mb < 4; ++mb) {
            const float* b0p = Ah + (16 * mb + g) * AH_STRIDE + 2 * tg + kb;
            const float* b1p = Ah + (16 * mb + 8 + g) * AH_STRIDE + 2 * tg + kb;
            float2 x0v = *(const float2*)b0p;
            float2 x1v = *(const float2*)b1p;
            float2 x2v = *(const float2*)(b0p + 8);
            float2 x3v = *(const float2*)(b1p + 8);
            bsplit(x0v.x, x0v.y, aH[mb][0], aL[mb][0]);
            bsplit(x1v.x, x1v.y, aH[mb][1], aL[mb][1]);
            bsplit(x2v.x, x2v.y, aH[mb][2], aL[mb][2]);
            bsplit(x3v.x, x3v.y, aH[mb][3], aL[mb][3]);
        }

#pragma unroll
        for (int j = 0; j < 7; ++j) {
            uint32_t bH0 = (uint32_t)w0[j], bH1 = (uint32_t)(w0[j] >> 32);
            uint32_t bL0 = (uint32_t)w1[j], bL1 = (uint32_t)(w1[j] >> 32);
#pragma unroll
            for (int mb = 0; mb < 4; ++mb) {
                mma16816(acc[mb][j], aH[mb], bH0, bH1);
                mma16816(acc[mb][j], aH[mb], bL0, bL1);
                mma16816(acc[mb][j], aL[mb], bH0, bH1);
            }
        }
    }
    __syncthreads();   // all mainloop reads of Ah done -> safe to overlay Cs

    // ---- bias + relu -> Cs (overlay Ah) ----
    float* Cs = Ah;
#pragma unroll
    for (int mb = 0; mb < 4; ++mb) {
        int rowa = (16 * mb + g) * AH_STRIDE;
        int rowb = (16 * mb + 8 + g) * AH_STRIDE;
#pragma unroll
        for (int j = 0; j < 7; ++j) {
            int q0 = (wid * 7 + j) * 8 + 2 * tg;
            if (q0 < PP) {
                Cs[rowa + q0] = fmaxf(acc[mb][j][0] + smf[P_PB + q0], 0.f);
                Cs[rowb + q0] = fmaxf(acc[mb][j][2] + smf[P_PB + q0], 0.f);
            }
            if (q0 + 1 < PP) {
                Cs[rowa + q0 + 1] = fmaxf(acc[mb][j][1] + smf[P_PB + q0 + 1], 0.f);
                Cs[rowb + q0 + 1] = fmaxf(acc[mb][j][3] + smf[P_PB + q0 + 1], 0.f);
            }
        }
    }
    __syncthreads();

    // ---- LN2 per sample row (8 warps x 8 rows) ----
    for (int r = wid * 8; r < wid * 8 + 8; ++r) {
        float sum = 0.f, sq = 0.f;
#pragma unroll
        for (int k = 0; k < 13; ++k) {
            int q = lane + 32 * k;
            if (q < PP) { float x = Cs[r * AH_STRIDE + q]; sum += x; sq += x * x; }
        }
        for (int o = 16; o; o >>= 1) {
            sum += __shfl_xor_sync(~0u, sum, o);
            sq  += __shfl_xor_sync(~0u, sq, o);
        }
        float mu = sum * (1.f / PP);
        float var = sq * (1.f / PP) - mu * mu;
        float rs = rsqrtf(var + 1e-5f);
#pragma unroll
        for (int k = 0; k < 13; ++k) {
            int q = lane + 32 * k;
            if (q < PP) {
                float x = Cs[r * AH_STRIDE + q];
                Cs[r * AH_STRIDE + q] = (x - mu) * rs * smf[P_PG + q] + smf[P_PB2 + q];
            }
        }
    }
    __syncthreads();

    // ---- 5x5 circular conv + 0.1*sigmoid + transposed write ----
    int b = s0 >> 12;
    int sw0 = s0 & (SEQ - 1);
    float kreg[25];
#pragma unroll
    for (int d = 0; d < 25; ++d) kreg[d] = smf[P_KS + d];
    float cc0 = smf[P_KS + 25];

    for (int item = tid; item < 800; item += 256) {
        int r8 = (item & 7) * 8;
        int pgi = item >> 3;
        int ii = pgi / 5, jj0 = (pgi % 5) * 4;
        int wy[5], wx[8];
#pragma unroll
        for (int dy = 0; dy < 5; ++dy) wy[dy] = ((ii + dy - 2 + 20) % 20) * 20;
#pragma unroll
        for (int dx = 0; dx < 8; ++dx) wx[dx] = (jj0 + dx - 2 + 20) % 20;

        float o[4][8];
#pragma unroll
        for (int rr = 0; rr < 8; ++rr) {
            const float* crow = Cs + (r8 + rr) * AH_STRIDE;
            float patch[5][8];
#pragma unroll
            for (int dy = 0; dy < 5; ++dy)
#pragma unroll
                for (int dx = 0; dx < 8; ++dx)
                    patch[dy][dx] = crow[wy[dy] + wx[dx]];
#pragma unroll
            for (int t = 0; t < 4; ++t) {
                float a = cc0;
#pragma unroll
                for (int du = 0; du < 5; ++du)
#pragma unroll
                    for (int dv = 0; dv < 5; ++dv)
                        a += kreg[du * 5 + dv] * patch[du][t + dv];
                o[t][rr] = 0.1f / (1.f + __expf(-a));
            }
        }
#pragma unroll
        for (int t = 0; t < 4; ++t) {
            int p = ii * 20 + jj0 + t;
            float* obase = out + ((size_t)(b * PP + p)) * SEQ + sw0 + r8;
            *(float4*)(obase)     = make_float4(o[t][0], o[t][1], o[t][2], o[t][3]);
            *(float4*)(obase + 4) = make_float4(o[t][4], o[t][5], o[t][6], o[t][7]);
        }
    }
}

// ---------------- persistent selection (deserialized) -----------------------
__device__ __forceinline__ void gbar(unsigned& target)
{
    __syncthreads();
    __threadfence();
    if (threadIdx.x == 0) {
        atomicAdd(&g_bar, 1u);
        while (*(volatile unsigned*)&g_bar < target) { }
    }
    __syncthreads();
    __threadfence();
}

__global__ void __launch_bounds__(256) select_persistent(float* __restrict__ out)
{
    int b = blockIdx.x & 7;        // batch
    int g = blockIdx.x >> 3;       // 0..31 within batch
    int tid = threadIdx.x, lane = tid & 31, wid = tid >> 5;
    unsigned target = 0;
    __shared__ float wvv[8];
    __shared__ int   wii[8];
    __shared__ float pw[4];
    __shared__ int   s_brk;

    // ---- init slices ----
    if (g < 16) {
        int s = g * 256 + tid;
        float m = g_m[b * SEQ + s];
        g_res[b * SEQ + s] = 1.f;
        g_v2[b * SEQ + s] = m * m;
    } else if (g == 16 || g == 17) {
        int p = (g - 16) * 256 + tid;
        if (p < PP) g_sel[b * PP + p] = 0;
    } else if (g == 18 && tid == 0) {
        g_done[b] = 0;
    }
    target += NBLK; gbar(target);

    for (int it = 0; it < ITERS; ++it) {
        // ---- PHASE A: activity, one warp per row (no block syncs) ----
        if (!g_done[b]) {
            int widx = g * 8 + wid;           // 0..255
            const float4* vv = (const float4*)(g_v2 + (size_t)b * SEQ);
            for (int p = widx; p < PP; p += 256) {
                if (g_sel[b * PP + p]) {
                    if (lane == 0) g_act[b * PP + p] = -1.f;
                    continue;
                }
                const float4* wp = (const float4*)(out + ((size_t)(b * PP + p)) * SEQ);
                float a = 0.f;
#pragma unroll 8
                for (int k = lane; k < SEQ / 4; k += 32) {
                    float4 x = wp[k]; float4 y = vv[k];
                    a += x.x * x.x * y.x + x.y * x.y * y.y
                       + x.z * x.z * y.z + x.w * x.w * y.w;
                }
                for (int o = 16; o; o >>= 1) a += __shfl_xor_sync(~0u, a, o);
                if (lane == 0) g_act[b * PP + p] = a;
            }
        }
        target += NBLK; gbar(target);

        // ---- PHASE B: leader block: done-check (prev iter partials) + argmax
        if (g == 0) {
            if (it > 0 && tid == 0 && !g_done[b]) {
                float t = 0.f;
#pragma unroll
                for (int i = 0; i < 32; ++i) t += g_part[b * 32 + i];
                if (t * (1.f / SEQ) < 0.05f) g_done[b] = 1;
            }
            __syncthreads();
            if (!g_done[b]) {
                float bv = -2.f; int bi = 0x7fffffff;
                for (int p = tid; p < PP; p += 256) {
                    float v = g_act[b * PP + p];
                    if (v > bv || (v == bv && p < bi)) { bv = v; bi = p; }
                }
                for (int o = 16; o; o >>= 1) {
                    float ov = __shfl_xor_sync(~0u, bv, o);
                    int   oi = __shfl_xor_sync(~0u, bi, o);
                    if (ov > bv || (ov == bv && oi < bi)) { bv = ov; bi = oi; }
                }
                if (lane == 0) { wvv[wid] = bv; wii[wid] = bi; }
                __syncthreads();
                if (tid == 0) {
                    float fv = -2.f; int fi = 0x7fffffff;
#pragma unroll
                    for (int i = 0; i < 8; ++i)
                        if (wvv[i] > fv || (wvv[i] == fv && wii[i] < fi)) { fv = wvv[i]; fi = wii[i]; }
                    g_sel[b * PP + fi] = 1;
                    g_pid[b] = fi;
                }
            }
        }
        target += NBLK; gbar(target);

        // ---- PHASE C: parallel res update, 128 elements per block ----
        if (!g_done[b]) {
            int pid = g_pid[b];
            float part = 0.f;
            if (tid < 128) {
                int s = g * 128 + tid;
                const float* row = out + ((size_t)(b * PP + pid)) * SEQ;
                float r = g_res[b * SEQ + s] - row[s] * 10.f;
                r = fmaxf(r, 0.f);
                g_res[b * SEQ + s] = r;
                part = r;
                float v = r * g_m[b * SEQ + s];
                g_v2[b * SEQ + s] = v * v;
            }
            for (int o = 16; o; o >>= 1) part += __shfl_xor_sync(~0u, part, o);
            if (lane == 0 && wid < 4) pw[wid] = part;
            __syncthreads();
            if (tid == 0) g_part[b * 32 + g] = pw[0] + pw[1] + pw[2] + pw[3];
        }
        target += NBLK; gbar(target);

        // ---- uniform early exit (done flags set in PHASE B) ----
        if (tid == 0) {
            int ad = 1;
#pragma unroll
            for (int i = 0; i < 8; ++i) ad &= g_done[i];
            s_brk = ad;
        }
        __syncthreads();
        if (s_brk) break;
        __syncthreads();
    }

    // ---- rescale selected rows x10 ----
    for (int p = g; p < PP; p += 32) {
        if (g_sel[b * PP + p]) {
            float4* wp = (float4*)(out + ((size_t)(b * PP + p)) * SEQ);
#pragma unroll
            for (int j = 0; j < 4; ++j) {
                int k = tid + 256 * j;
                float4 x = wp[k];
                x.x *= 10.f; x.y *= 10.f; x.z *= 10.f; x.w *= 10.f;
                wp[k] = x;
            }
        }
    }
}

// ---------------- launch --------------------------------------------------
extern "C" void kernel_launch(void* const* d_in, const int* in_sizes, int n_in,
                              void* d_out, int out_size)
{
    const float* x0     = (const float*)d_in[0];
    const float* fc1_w  = (const float*)d_in[1];
    const float* fc1_b  = (const float*)d_in[2];
    const float* ln1_g  = (const float*)d_in[3];
    const float* ln1_b  = (const float*)d_in[4];
    const float* fc2_w  = (const float*)d_in[5];
    const float* fc2_b  = (const float*)d_in[6];
    const float* ln2_g  = (const float*)d_in[7];
    const float* ln2_b  = (const float*)d_in[8];
    const float* c1w    = (const float*)d_in[9];
    const float* c1b    = (const float*)d_in[10];
    const float* c2w    = (const float*)d_in[11];
    const float* c2b    = (const float*)d_in[12];
    float* out = (float*)d_out;

    cudaFuncSetAttribute(kernelB, cudaFuncAttributeMaxDynamicSharedMemorySize, SMEM_TOTAL);

    prep_kernel<<<701, 256>>>(fc2_w, c1w, c1b, c2w, c2b);
    kernelB<<<NSAMP / BM, 256, SMEM_TOTAL>>>(x0, fc1_w, fc1_b, ln1_g, ln1_b,
                                             fc2_b, ln2_g, ln2_b, out);
    select_persistent<<<NBLK, 256>>>(out);
}

// round 12
// speedup vs baseline: 1.6260x; 1.6260x over previous
#include <cuda_runtime.h>
#include <cuda_bf16.h>
#include <math.h>
#include <stdint.h>

// Problem constants
#define BATCH 8
#define SEQ   4096
#define PP    400           // 20x20
#define NSAMP (BATCH*SEQ)   // 32768
#define ITERS 12
#define NBLK  256           // persistent selection grid

// GEMM: M=32768 (64/CTA), N=448 (56 n8-tiles, 7 per warp), K=400 (25 k16-steps)
#define NK16  25
#define NNT   56

typedef unsigned long long u64;

// ---------------- scratch (static __device__, no allocations) ----------------
__device__ unsigned g_Bfrag[NK16 * NNT * 2 * 64];  // [k16][nt][plane][lane][2] u32
__device__ float  g_m[NSAMP];
__device__ float  g_keff[25];
__device__ float  g_c;
__device__ float  g_act[BATCH * PP];
__device__ int    g_sel[BATCH * PP];
__device__ int    g_done[BATCH];
__device__ int    g_pid[BATCH];
__device__ float  g_part[BATCH * 32];
__device__ float  g_res[BATCH * SEQ];
__device__ float  g_v2[BATCH * SEQ];
__device__ unsigned g_bar;

// ---------------- helpers ----------------
__device__ __forceinline__ void bsplit(float lo, float hi, uint32_t& h, uint32_t& l)
{
    asm("cvt.rn.bf16x2.f32 %0,%1,%2;" : "=r"(h) : "f"(hi), "f"(lo));
    float hlo = __uint_as_float(h << 16);
    float hhi = __uint_as_float(h & 0xffff0000u);
    asm("cvt.rn.bf16x2.f32 %0,%1,%2;" : "=r"(l) : "f"(hi - hhi), "f"(lo - hlo));
}
__device__ __forceinline__ void mma16816(float* c, const uint32_t* a,
                                         uint32_t b0, uint32_t b1)
{
    asm volatile(
        "mma.sync.aligned.m16n8k16.row.col.f32.bf16.bf16.f32 "
        "{%0,%1,%2,%3},{%4,%5,%6,%7},{%8,%9},{%0,%1,%2,%3};"
        : "+f"(c[0]), "+f"(c[1]), "+f"(c[2]), "+f"(c[3])
        : "r"(a[0]), "r"(a[1]), "r"(a[2]), "r"(a[3]), "r"(b0), "r"(b1));
}

// ---------------- prep: B fragment planes + conv compose + barrier reset -----
__global__ void prep_kernel(const float* __restrict__ fc2_w,
                            const float* __restrict__ c1w, const float* __restrict__ c1b,
                            const float* __restrict__ c2w, const float* __restrict__ c2b)
{
    if (blockIdx.x < 700) {
        int e = blockIdx.x * 256 + threadIdx.x;   // [k16][nt][plane][lane][reg]
        int reg   = e & 1;
        int lane  = (e >> 1) & 31;
        int plane = (e >> 6) & 1;
        int r     = e >> 7;                        // 0..1399
        int nt  = r % NNT;
        int k16 = r / NNT;
        int g = lane >> 2, tg = lane & 3;
        int n  = nt * 8 + g;
        int kr = k16 * 16 + tg * 2 + reg * 8;
        float v0 = (n < PP) ? fc2_w[n * PP + kr] : 0.f;
        float v1 = (n < PP) ? fc2_w[n * PP + kr + 1] : 0.f;
        uint32_t h, l;
        bsplit(v0, v1, h, l);
        g_Bfrag[(((size_t)r * 2 + plane) * 32 + lane) * 2 + reg] = plane ? l : h;
        return;
    }
    // last block: keff compose + g_bar reset
    __shared__ float s1w[45], s1b[5], s2w[450], s2b[10], part[250];
    int t = threadIdx.x;
    if (t == 0) g_bar = 0u;
    if (t < 45)  s1w[t] = c1w[t];
    if (t < 5)   s1b[t] = c1b[t];
    for (int i = t; i < 450; i += 256) s2w[i] = c2w[i];
    if (t < 10)  s2b[t] = c2b[t];
    __syncthreads();
    if (t < 250) {
        int uv = t / 10, oc = t % 10;
        int u = uv / 5, v = uv % 5;
        float acc = 0.f;
        for (int ic = 0; ic < 5; ++ic)
#pragma unroll
            for (int ay = 0; ay < 3; ++ay) {
                int by = u - ay; if (by < 0 || by > 2) continue;
#pragma unroll
                for (int ax = 0; ax < 3; ++ax) {
                    int bx = v - ax; if (bx < 0 || bx > 2) continue;
                    acc += s2w[((oc * 5 + ic) * 3 + by) * 3 + bx] * s1w[(ic * 3 + ay) * 3 + ax];
                }
            }
        part[t] = acc;
    }
    __syncthreads();
    if (t < 25) {
        float acc = 0.f;
#pragma unroll
        for (int oc = 0; oc < 10; ++oc) acc += part[t * 10 + oc];
        g_keff[t] = acc * 0.1f;
    } else if (t == 25) {
        float acc = 0.f;
        for (int oc = 0; oc < 10; ++oc) {
            float t2 = s2b[oc];
            for (int ic = 0; ic < 5; ++ic) {
                float sw = 0.f;
#pragma unroll
                for (int bb = 0; bb < 9; ++bb) sw += s2w[(oc * 5 + ic) * 9 + bb];
                t2 += s1b[ic] * sw;
            }
            acc += t2;
        }
        g_c = acc * 0.1f;
    }
}

// ---- kernel B: EXACT R10 version (proven fastest) --------------------------
#define BM 64
#define AH_STRIDE 404
#define REGION (BM * AH_STRIDE)
#define P_FW   (REGION)
#define P_FB   (P_FW + 1200)
#define P_L1G  (P_FB + PP)
#define P_L1B  (P_L1G + PP)
#define P_PB   (P_L1B + PP)
#define P_PG   (P_PB + PP)
#define P_PB2  (P_PG + PP)
#define P_KS   (P_PB2 + PP)
#define SMEM_TOTAL ((P_KS + 32) * 4)

__global__ void __launch_bounds__(256, 1) kernelB(
    const float* __restrict__ x0,
    const float* __restrict__ fc1_w, const float* __restrict__ fc1_b,
    const float* __restrict__ ln1_g, const float* __restrict__ ln1_b,
    const float* __restrict__ fc2_b, const float* __restrict__ ln2_g,
    const float* __restrict__ ln2_b, float* __restrict__ out)
{
    extern __shared__ float smf[];
    float* Ah = smf;

    int tid = threadIdx.x, lane = tid & 31, wid = tid >> 5;
    int s0 = blockIdx.x * BM;

    for (int i = tid; i < 1200; i += 256) smf[P_FW + i] = fc1_w[i];
    for (int i = tid; i < PP; i += 256) {
        smf[P_FB + i] = fc1_b[i]; smf[P_L1G + i] = ln1_g[i]; smf[P_L1B + i] = ln1_b[i];
        smf[P_PB + i] = fc2_b[i]; smf[P_PG + i] = ln2_g[i]; smf[P_PB2 + i] = ln2_b[i];
    }
    if (tid < 26) smf[P_KS + tid] = (tid < 25) ? g_keff[tid] : g_c;
    __syncthreads();

    // ---- fused fc1 + relu + ln1 into Ah ----
    for (int r = wid; r < BM; r += 8) {
        int ss = s0 + r;
        const float* xp = x0 + (size_t)ss * 3;
        float xa = xp[0], xb = xp[1], xc = xp[2];
        if (lane == 0) g_m[ss] = (xa + xb + xc) * (1.f / 3.f);
        float v[13];
        float sum = 0.f, sq = 0.f;
#pragma unroll
        for (int k = 0; k < 13; ++k) {
            int q = lane + 32 * k;
            float h = 0.f;
            if (q < PP) {
                h = fmaxf(xa * smf[P_FW + q * 3] + xb * smf[P_FW + q * 3 + 1]
                        + xc * smf[P_FW + q * 3 + 2] + smf[P_FB + q], 0.f);
            }
            v[k] = h; sum += h; sq += h * h;
        }
        for (int o = 16; o; o >>= 1) {
            sum += __shfl_xor_sync(~0u, sum, o);
            sq  += __shfl_xor_sync(~0u, sq, o);
        }
        float mu = sum * (1.f / PP);
        float var = sq * (1.f / PP) - mu * mu;
        float rs = rsqrtf(var + 1e-5f);
#pragma unroll
        for (int k = 0; k < 13; ++k) {
            int q = lane + 32 * k;
            if (q < PP) Ah[r * AH_STRIDE + q] = (v[k] - mu) * rs * smf[P_L1G + q] + smf[P_L1B + q];
        }
    }
    __syncthreads();

    // ---- mma.sync bf16-split mainloop (R10 form, no hoist) ----
    int g = lane >> 2, tg = lane & 3;
    float acc[4][7][4];
#pragma unroll
    for (int mb = 0; mb < 4; ++mb)
#pragma unroll
        for (int j = 0; j < 7; ++j)
#pragma unroll
            for (int i = 0; i < 4; ++i) acc[mb][j][i] = 0.f;

    const u64* bfr = (const u64*)g_Bfrag;

    for (int k16 = 0; k16 < NK16; ++k16) {
        int kb = k16 * 16;
        uint32_t aH[4][4], aL[4][4];
#pragma unroll
        for (int mb = 0; mb < 4; ++mb) {
            const float* b0p = Ah + (16 * mb + g) * AH_STRIDE + 2 * tg + kb;
            const float* b1p = Ah + (16 * mb + 8 + g) * AH_STRIDE + 2 * tg + kb;
            float2 x0v = *(const float2*)b0p;
            float2 x1v = *(const float2*)b1p;
            float2 x2v = *(const float2*)(b0p + 8);
            float2 x3v = *(const float2*)(b1p + 8);
            bsplit(x0v.x, x0v.y, aH[mb][0], aL[mb][0]);
            bsplit(x1v.x, x1v.y, aH[mb][1], aL[mb][1]);
            bsplit(x2v.x, x2v.y, aH[mb][2], aL[mb][2]);
            bsplit(x3v.x, x3v.y, aH[mb][3], aL[mb][3]);
        }

        size_t base = ((size_t)(k16 * NNT + wid * 7)) * 64 + lane;
#pragma unroll
        for (int j = 0; j < 7; ++j) {
            u64 w0 = bfr[base + (size_t)j * 64];
            u64 w1 = bfr[base + (size_t)j * 64 + 32];
            uint32_t bH0 = (uint32_t)w0, bH1 = (uint32_t)(w0 >> 32);
            uint32_t bL0 = (uint32_t)w1, bL1 = (uint32_t)(w1 >> 32);
#pragma unroll
            for (int mb = 0; mb < 4; ++mb) {
                mma16816(acc[mb][j], aH[mb], bH0, bH1);
                mma16816(acc[mb][j], aH[mb], bL0, bL1);
                mma16816(acc[mb][j], aL[mb], bH0, bH1);
            }
        }
    }
    __syncthreads();

    // ---- bias + relu -> Cs (overlay Ah) ----
    float* Cs = Ah;
#pragma unroll
    for (int mb = 0; mb < 4; ++mb) {
        int rowa = (16 * mb + g) * AH_STRIDE;
        int rowb = (16 * mb + 8 + g) * AH_STRIDE;
#pragma unroll
        for (int j = 0; j < 7; ++j) {
            int q0 = (wid * 7 + j) * 8 + 2 * tg;
            if (q0 < PP) {
                Cs[rowa + q0] = fmaxf(acc[mb][j][0] + smf[P_PB + q0], 0.f);
                Cs[rowb + q0] = fmaxf(acc[mb][j][2] + smf[P_PB + q0], 0.f);
            }
            if (q0 + 1 < PP) {
                Cs[rowa + q0 + 1] = fmaxf(acc[mb][j][1] + smf[P_PB + q0 + 1], 0.f);
                Cs[rowb + q0 + 1] = fmaxf(acc[mb][j][3] + smf[P_PB + q0 + 1], 0.f);
            }
        }
    }
    __syncthreads();

    // ---- LN2 per sample row ----
    for (int r = wid * 8; r < wid * 8 + 8; ++r) {
        float sum = 0.f, sq = 0.f;
#pragma unroll
        for (int k = 0; k < 13; ++k) {
            int q = lane + 32 * k;
            if (q < PP) { float x = Cs[r * AH_STRIDE + q]; sum += x; sq += x * x; }
        }
        for (int o = 16; o; o >>= 1) {
            sum += __shfl_xor_sync(~0u, sum, o);
            sq  += __shfl_xor_sync(~0u, sq, o);
        }
        float mu = sum * (1.f / PP);
        float var = sq * (1.f / PP) - mu * mu;
        float rs = rsqrtf(var + 1e-5f);
#pragma unroll
        for (int k = 0; k < 13; ++k) {
            int q = lane + 32 * k;
            if (q < PP) {
                float x = Cs[r * AH_STRIDE + q];
                Cs[r * AH_STRIDE + q] = (x - mu) * rs * smf[P_PG + q] + smf[P_PB2 + q];
            }
        }
    }
    __syncthreads();

    // ---- 5x5 circular conv + 0.1*sigmoid + transposed write ----
    int b = s0 >> 12;
    int sw0 = s0 & (SEQ - 1);
    float kreg[25];
#pragma unroll
    for (int d = 0; d < 25; ++d) kreg[d] = smf[P_KS + d];
    float cc0 = smf[P_KS + 25];

    for (int item = tid; item < 800; item += 256) {
        int r8 = (item & 7) * 8;
        int pgi = item >> 3;
        int ii = pgi / 5, jj0 = (pgi % 5) * 4;
        int wy[5], wx[8];
#pragma unroll
        for (int dy = 0; dy < 5; ++dy) wy[dy] = ((ii + dy - 2 + 20) % 20) * 20;
#pragma unroll
        for (int dx = 0; dx < 8; ++dx) wx[dx] = (jj0 + dx - 2 + 20) % 20;

        float o[4][8];
#pragma unroll
        for (int rr = 0; rr < 8; ++rr) {
            const float* crow = Cs + (r8 + rr) * AH_STRIDE;
            float patch[5][8];
#pragma unroll
            for (int dy = 0; dy < 5; ++dy)
#pragma unroll
                for (int dx = 0; dx < 8; ++dx)
                    patch[dy][dx] = crow[wy[dy] + wx[dx]];
#pragma unroll
            for (int t = 0; t < 4; ++t) {
                float a = cc0;
#pragma unroll
                for (int du = 0; du < 5; ++du)
#pragma unroll
                    for (int dv = 0; dv < 5; ++dv)
                        a += kreg[du * 5 + dv] * patch[du][t + dv];
                o[t][rr] = 0.1f / (1.f + __expf(-a));
            }
        }
#pragma unroll
        for (int t = 0; t < 4; ++t) {
            int p = ii * 20 + jj0 + t;
            float* obase = out + ((size_t)(b * PP + p)) * SEQ + sw0 + r8;
            *(float4*)(obase)     = make_float4(o[t][0], o[t][1], o[t][2], o[t][3]);
            *(float4*)(obase + 4) = make_float4(o[t][4], o[t][5], o[t][6], o[t][7]);
        }
    }
}

// ---------------- persistent selection: R10 + parallel update ---------------
__device__ __forceinline__ void gbar(unsigned& target)
{
    __syncthreads();
    __threadfence();
    if (threadIdx.x == 0) {
        atomicAdd(&g_bar, 1u);
        while (*(volatile unsigned*)&g_bar < target) { }
    }
    __syncthreads();
    __threadfence();
}

__global__ void __launch_bounds__(256) select_persistent(float* __restrict__ out)
{
    int b = blockIdx.x & 7;        // batch
    int g = blockIdx.x >> 3;       // 0..31 within batch
    int tid = threadIdx.x, lane = tid & 31, wid = tid >> 5;
    unsigned target = 0;
    int done_b = 0;
    __shared__ float ws[8];
    __shared__ float wvv[8];
    __shared__ int   wii[8];
    __shared__ float pw[4];
    __shared__ int   s_done, s_brk;

    // ---- init slices ----
    if (g < 16) {
        int s = g * 256 + tid;
        float m = g_m[b * SEQ + s];
        g_res[b * SEQ + s] = 1.f;
        g_v2[b * SEQ + s] = m * m;
    } else if (g == 16 || g == 17) {
        int p = (g - 16) * 256 + tid;
        if (p < PP) g_sel[b * PP + p] = 0;
    } else if (g == 18 && tid == 0) {
        g_done[b] = 0;
    }
    target += NBLK; gbar(target);

    for (int it = 0; it < ITERS; ++it) {
        // ---- PHASE A: done-check (from prev iter partials) + activity ----
        if (!done_b && it > 0) {
            if (tid == 0) {
                float t = 0.f;
#pragma unroll
                for (int i = 0; i < 32; ++i) t += g_part[b * 32 + i];
                s_done = (t * (1.f / SEQ) < 0.05f) ? 1 : 0;
            }
            __syncthreads();
            if (s_done) {
                done_b = 1;
                if (g == 0 && tid == 0) g_done[b] = 1;
            }
            __syncthreads();
        }
        if (!done_b) {
            const float4* vv = (const float4*)(g_v2 + (size_t)b * SEQ);
            for (int p = g; p < PP; p += 32) {
                if (g_sel[b * PP + p]) {
                    if (tid == 0) g_act[b * PP + p] = -1.f;
                    continue;
                }
                const float4* wp = (const float4*)(out + ((size_t)(b * PP + p)) * SEQ);
                float a = 0.f;
#pragma unroll
                for (int j = 0; j < 4; ++j) {
                    int k = tid + 256 * j;
                    float4 x = wp[k]; float4 y = vv[k];
                    a += x.x * x.x * y.x + x.y * x.y * y.y
                       + x.z * x.z * y.z + x.w * x.w * y.w;
                }
                for (int o = 16; o; o >>= 1) a += __shfl_xor_sync(~0u, a, o);
                if (lane == 0) ws[wid] = a;
                __syncthreads();
                if (tid == 0) {
                    float t = 0.f;
#pragma unroll
                    for (int i = 0; i < 8; ++i) t += ws[i];
                    g_act[b * PP + p] = t;
                }
                __syncthreads();
            }
        }
        target += NBLK; gbar(target);

        // ---- PHASE B: all-done break + leader argmax ----
        if (tid == 0) {
            int ad = 1;
#pragma unroll
            for (int i = 0; i < 8; ++i) ad &= g_done[i];
            s_brk = ad;
        }
        __syncthreads();
        if (s_brk) break;

        if (g == 0 && !done_b) {
            float bv = -2.f; int bi = 0x7fffffff;
            for (int p = tid; p < PP; p += 256) {
                float v = g_act[b * PP + p];
                if (v > bv || (v == bv && p < bi)) { bv = v; bi = p; }
            }
            for (int o = 16; o; o >>= 1) {
                float ov = __shfl_xor_sync(~0u, bv, o);
                int   oi = __shfl_xor_sync(~0u, bi, o);
                if (ov > bv || (ov == bv && oi < bi)) { bv = ov; bi = oi; }
            }
            if (lane == 0) { wvv[wid] = bv; wii[wid] = bi; }
            __syncthreads();
            if (tid == 0) {
                float fv = -2.f; int fi = 0x7fffffff;
#pragma unroll
                for (int i = 0; i < 8; ++i)
                    if (wvv[i] > fv || (wvv[i] == fv && wii[i] < fi)) { fv = wvv[i]; fi = wii[i]; }
                g_sel[b * PP + fi] = 1;
                g_pid[b] = fi;
            }
        }
        target += NBLK; gbar(target);

        // ---- PHASE C: parallel res/v2 update (128 elems per block) ----
        if (!done_b) {
            int pid = g_pid[b];
            float part = 0.f;
            if (tid < 128) {
                int s = g * 128 + tid;
                const float* row = out + ((size_t)(b * PP + pid)) * SEQ;
                float r = g_res[b * SEQ + s] - row[s] * 10.f;
                r = fmaxf(r, 0.f);
                g_res[b * SEQ + s] = r;
                part = r;
                float v = r * g_m[b * SEQ + s];
                g_v2[b * SEQ + s] = v * v;
            }
            for (int o = 16; o; o >>= 1) part += __shfl_xor_sync(~0u, part, o);
            if (lane == 0 && wid < 4) pw[wid] = part;
            __syncthreads();
            if (tid == 0) g_part[b * 32 + g] = pw[0] + pw[1] + pw[2] + pw[3];
        }
        target += NBLK; gbar(target);
    }

    // ---- rescale selected rows x10 ----
    for (int p = g; p < PP; p += 32) {
        if (g_sel[b * PP + p]) {
            float4* wp = (float4*)(out + ((size_t)(b * PP + p)) * SEQ);
#pragma unroll
            for (int j = 0; j < 4; ++j) {
                int k = tid + 256 * j;
                float4 x = wp[k];
                x.x *= 10.f; x.y *= 10.f; x.z *= 10.f; x.w *= 10.f;
                wp[k] = x;
            }
        }
    }
}

// ---------------- launch --------------------------------------------------
extern "C" void kernel_launch(void* const* d_in, const int* in_sizes, int n_in,
                              void* d_out, int out_size)
{
    const float* x0     = (const float*)d_in[0];
    const float* fc1_w  = (const float*)d_in[1];
    const float* fc1_b  = (const float*)d_in[2];
    const float* ln1_g  = (const float*)d_in[3];
    const float* ln1_b  = (const float*)d_in[4];
    const float* fc2_w  = (const float*)d_in[5];
    const float* fc2_b  = (const float*)d_in[6];
    const float* ln2_g  = (const float*)d_in[7];
    const float* ln2_b  = (const float*)d_in[8];
    const float* c1w    = (const float*)d_in[9];
    const float* c1b    = (const float*)d_in[10];
    const float* c2w    = (const float*)d_in[11];
    const float* c2b    = (const float*)d_in[12];
    float* out = (float*)d_out;

    cudaFuncSetAttribute(kernelB, cudaFuncAttributeMaxDynamicSharedMemorySize, SMEM_TOTAL);

    prep_kernel<<<701, 256>>>(fc2_w, c1w, c1b, c2w, c2b);
    kernelB<<<NSAMP / BM, 256, SMEM_TOTAL>>>(x0, fc1_w, fc1_b, ln1_g, ln1_b,
                                             fc2_b, ln2_g, ln2_b, out);
    select_persistent<<<NBLK, 256>>>(out);
}

// round 15
// speedup vs baseline: 1.7175x; 1.0562x over previous
#include <cuda_runtime.h>
#include <cuda_bf16.h>
#include <math.h>
#include <stdint.h>

// Problem constants
#define BATCH 8
#define SEQ   4096
#define PP    400           // 20x20
#define NSAMP (BATCH*SEQ)   // 32768
#define ITERS 12
#define NBLK  256           // persistent selection grid

// GEMM: M=32768 (64/CTA), N=448 (56 n8-tiles), K=400 (25 k16-steps)
#define NK16  25
#define NNT   56
#define TB    512           // kernelB threads (16 warps)

typedef unsigned long long u64;

// ---------------- scratch (static __device__, no allocations) ----------------
__device__ unsigned g_Bfrag[NK16 * NNT * 2 * 64];  // [k16][nt][plane][lane][2] u32
__device__ float  g_m[NSAMP];
__device__ float  g_keff[25];
__device__ float  g_c;
__device__ float  g_act[BATCH * PP];
__device__ int    g_sel[BATCH * PP];
__device__ int    g_done[BATCH];
__device__ float  g_part[BATCH * 32];
__device__ float  g_res[BATCH * SEQ];
__device__ float  g_v2[BATCH * SEQ];
__device__ unsigned g_bar;

// ---------------- helpers ----------------
__device__ __forceinline__ void bsplit(float lo, float hi, uint32_t& h, uint32_t& l)
{
    asm("cvt.rn.bf16x2.f32 %0,%1,%2;" : "=r"(h) : "f"(hi), "f"(lo));
    float hlo = __uint_as_float(h << 16);
    float hhi = __uint_as_float(h & 0xffff0000u);
    asm("cvt.rn.bf16x2.f32 %0,%1,%2;" : "=r"(l) : "f"(hi - hhi), "f"(lo - hlo));
}
__device__ __forceinline__ void mma16816(float* c, const uint32_t* a,
                                         uint32_t b0, uint32_t b1)
{
    asm volatile(
        "mma.sync.aligned.m16n8k16.row.col.f32.bf16.bf16.f32 "
        "{%0,%1,%2,%3},{%4,%5,%6,%7},{%8,%9},{%0,%1,%2,%3};"
        : "+f"(c[0]), "+f"(c[1]), "+f"(c[2]), "+f"(c[3])
        : "r"(a[0]), "r"(a[1]), "r"(a[2]), "r"(a[3]), "r"(b0), "r"(b1));
}

// ---------------- prep: B fragment planes + conv compose + barrier reset -----
__global__ void prep_kernel(const float* __restrict__ fc2_w,
                            const float* __restrict__ c1w, const float* __restrict__ c1b,
                            const float* __restrict__ c2w, const float* __restrict__ c2b)
{
    if (blockIdx.x < 700) {
        int e = blockIdx.x * 256 + threadIdx.x;   // [k16][nt][plane][lane][reg]
        int reg   = e & 1;
        int lane  = (e >> 1) & 31;
        int plane = (e >> 6) & 1;
        int r     = e >> 7;                        // 0..1399
        int nt  = r % NNT;
        int k16 = r / NNT;
        int g = lane >> 2, tg = lane & 3;
        int n  = nt * 8 + g;
        int kr = k16 * 16 + tg * 2 + reg * 8;
        float v0 = (n < PP) ? fc2_w[n * PP + kr] : 0.f;
        float v1 = (n < PP) ? fc2_w[n * PP + kr + 1] : 0.f;
        uint32_t h, l;
        bsplit(v0, v1, h, l);
        g_Bfrag[(((size_t)r * 2 + plane) * 32 + lane) * 2 + reg] = plane ? l : h;
        return;
    }
    // last block: keff compose + g_bar reset
    __shared__ float s1w[45], s1b[5], s2w[450], s2b[10], part[250];
    int t = threadIdx.x;
    if (t == 0) g_bar = 0u;
    if (t < 45)  s1w[t] = c1w[t];
    if (t < 5)   s1b[t] = c1b[t];
    for (int i = t; i < 450; i += 256) s2w[i] = c2w[i];
    if (t < 10)  s2b[t] = c2b[t];
    __syncthreads();
    if (t < 250) {
        int uv = t / 10, oc = t % 10;
        int u = uv / 5, v = uv % 5;
        float acc = 0.f;
        for (int ic = 0; ic < 5; ++ic)
#pragma unroll
            for (int ay = 0; ay < 3; ++ay) {
                int by = u - ay; if (by < 0 || by > 2) continue;
#pragma unroll
                for (int ax = 0; ax < 3; ++ax) {
                    int bx = v - ax; if (bx < 0 || bx > 2) continue;
                    acc += s2w[((oc * 5 + ic) * 3 + by) * 3 + bx] * s1w[(ic * 3 + ay) * 3 + ax];
                }
            }
        part[t] = acc;
    }
    __syncthreads();
    if (t < 25) {
        float acc = 0.f;
#pragma unroll
        for (int oc = 0; oc < 10; ++oc) acc += part[t * 10 + oc];
        g_keff[t] = acc * 0.1f;
    } else if (t == 25) {
        float acc = 0.f;
        for (int oc = 0; oc < 10; ++oc) {
            float t2 = s2b[oc];
            for (int ic = 0; ic < 5; ++ic) {
                float sw = 0.f;
#pragma unroll
                for (int bb = 0; bb < 9; ++bb) sw += s2w[(oc * 5 + ic) * 9 + bb];
                t2 += s1b[ic] * sw;
            }
            acc += t2;
        }
        g_c = acc * 0.1f;
    }
}

// ---- kernel B: 16 warps; fc1+ln1 + mma.sync bf16-split + ln2 + conv --------
#define BM 64
#define AH_STRIDE 404
#define REGION (BM * AH_STRIDE)
#define P_FW   (REGION)
#define P_FB   (P_FW + 1200)
#define P_L1G  (P_FB + PP)
#define P_L1B  (P_L1G + PP)
#define P_PB   (P_L1B + PP)
#define P_PG   (P_PB + PP)
#define P_PB2  (P_PG + PP)
#define P_KS   (P_PB2 + PP)
#define SMEM_TOTAL ((P_KS + 32) * 4)

__global__ void __launch_bounds__(TB, 1) kernelB(
    const float* __restrict__ x0,
    const float* __restrict__ fc1_w, const float* __restrict__ fc1_b,
    const float* __restrict__ ln1_g, const float* __restrict__ ln1_b,
    const float* __restrict__ fc2_b, const float* __restrict__ ln2_g,
    const float* __restrict__ ln2_b, float* __restrict__ out)
{
    extern __shared__ float smf[];
    float* Ah = smf;

    int tid = threadIdx.x, lane = tid & 31, wid = tid >> 5;   // 16 warps
    int s0 = blockIdx.x * BM;

    for (int i = tid; i < 1200; i += TB) smf[P_FW + i] = fc1_w[i];
    for (int i = tid; i < PP; i += TB) {
        smf[P_FB + i] = fc1_b[i]; smf[P_L1G + i] = ln1_g[i]; smf[P_L1B + i] = ln1_b[i];
        smf[P_PB + i] = fc2_b[i]; smf[P_PG + i] = ln2_g[i]; smf[P_PB2 + i] = ln2_b[i];
    }
    if (tid < 26) smf[P_KS + tid] = (tid < 25) ? g_keff[tid] : g_c;
    __syncthreads();

    // ---- fused fc1 + relu + ln1 into Ah (one warp per sample, 4 rounds) ----
    for (int r = wid; r < BM; r += 16) {
        int ss = s0 + r;
        const float* xp = x0 + (size_t)ss * 3;
        float xa = xp[0], xb = xp[1], xc = xp[2];
        if (lane == 0) g_m[ss] = (xa + xb + xc) * (1.f / 3.f);
        float v[13];
        float sum = 0.f, sq = 0.f;
#pragma unroll
        for (int k = 0; k < 13; ++k) {
            int q = lane + 32 * k;
            float h = 0.f;
            if (q < PP) {
                h = fmaxf(xa * smf[P_FW + q * 3] + xb * smf[P_FW + q * 3 + 1]
                        + xc * smf[P_FW + q * 3 + 2] + smf[P_FB + q], 0.f);
            }
            v[k] = h; sum += h; sq += h * h;
        }
        for (int o = 16; o; o >>= 1) {
            sum += __shfl_xor_sync(~0u, sum, o);
            sq  += __shfl_xor_sync(~0u, sq, o);
        }
        float mu = sum * (1.f / PP);
        float var = sq * (1.f / PP) - mu * mu;
        float rs = rsqrtf(var + 1e-5f);
#pragma unroll
        for (int k = 0; k < 13; ++k) {
            int q = lane + 32 * k;
            if (q < PP) Ah[r * AH_STRIDE + q] = (v[k] - mu) * rs * smf[P_L1G + q] + smf[P_L1B + q];
        }
    }
    __syncthreads();

    // ---- mma.sync bf16-split mainloop ----
    // warp = (mhalf, ng): 2 m16-blocks (mb = mhalf*2 + i) x 7 n8-tiles (nt = ng*7+j)
    int mhalf = wid >> 3, ng = wid & 7;
    int g = lane >> 2, tg = lane & 3;
    float acc[2][7][4];
#pragma unroll
    for (int mi = 0; mi < 2; ++mi)
#pragma unroll
        for (int j = 0; j < 7; ++j)
#pragma unroll
            for (int i = 0; i < 4; ++i) acc[mi][j][i] = 0.f;

    const u64* bfr = (const u64*)g_Bfrag;

    for (int k16 = 0; k16 < NK16; ++k16) {
        int kb = k16 * 16;
        uint32_t aH[2][4], aL[2][4];
#pragma unroll
        for (int mi = 0; mi < 2; ++mi) {
            int mb = mhalf * 2 + mi;
            const float* b0p = Ah + (16 * mb + g) * AH_STRIDE + 2 * tg + kb;
            const float* b1p = Ah + (16 * mb + 8 + g) * AH_STRIDE + 2 * tg + kb;
            float2 x0v = *(const float2*)b0p;
            float2 x1v = *(const float2*)b1p;
            float2 x2v = *(const float2*)(b0p + 8);
            float2 x3v = *(const float2*)(b1p + 8);
            bsplit(x0v.x, x0v.y, aH[mi][0], aL[mi][0]);
            bsplit(x1v.x, x1v.y, aH[mi][1], aL[mi][1]);
            bsplit(x2v.x, x2v.y, aH[mi][2], aL[mi][2]);
            bsplit(x3v.x, x3v.y, aH[mi][3], aL[mi][3]);
        }

        size_t base = ((size_t)(k16 * NNT + ng * 7)) * 64 + lane;
#pragma unroll
        for (int j = 0; j < 7; ++j) {
            u64 w0 = bfr[base + (size_t)j * 64];
            u64 w1 = bfr[base + (size_t)j * 64 + 32];
            uint32_t bH0 = (uint32_t)w0, bH1 = (uint32_t)(w0 >> 32);
            uint32_t bL0 = (uint32_t)w1, bL1 = (uint32_t)(w1 >> 32);
#pragma unroll
            for (int mi = 0; mi < 2; ++mi) {
                mma16816(acc[mi][j], aH[mi], bH0, bH1);
                mma16816(acc[mi][j], aH[mi], bL0, bL1);
                mma16816(acc[mi][j], aL[mi], bH0, bH1);
            }
        }
    }
    __syncthreads();

    // ---- bias + relu -> Cs (overlay Ah) ----
    float* Cs = Ah;
#pragma unroll
    for (int mi = 0; mi < 2; ++mi) {
        int mb = mhalf * 2 + mi;
        int rowa = (16 * mb + g) * AH_STRIDE;
        int rowb = (16 * mb + 8 + g) * AH_STRIDE;
#pragma unroll
        for (int j = 0; j < 7; ++j) {
            int q0 = (ng * 7 + j) * 8 + 2 * tg;
            if (q0 < PP) {
                Cs[rowa + q0] = fmaxf(acc[mi][j][0] + smf[P_PB + q0], 0.f);
                Cs[rowb + q0] = fmaxf(acc[mi][j][2] + smf[P_PB + q0], 0.f);
            }
            if (q0 + 1 < PP) {
                Cs[rowa + q0 + 1] = fmaxf(acc[mi][j][1] + smf[P_PB + q0 + 1], 0.f);
                Cs[rowb + q0 + 1] = fmaxf(acc[mi][j][3] + smf[P_PB + q0 + 1], 0.f);
            }
        }
    }
    __syncthreads();

    // ---- LN2 per sample row (16 warps x 4 rows) ----
    for (int r = wid * 4; r < wid * 4 + 4; ++r) {
        float sum = 0.f, sq = 0.f;
#pragma unroll
        for (int k = 0; k < 13; ++k) {
            int q = lane + 32 * k;
            if (q < PP) { float x = Cs[r * AH_STRIDE + q]; sum += x; sq += x * x; }
        }
        for (int o = 16; o; o >>= 1) {
            sum += __shfl_xor_sync(~0u, sum, o);
            sq  += __shfl_xor_sync(~0u, sq, o);
        }
        float mu = sum * (1.f / PP);
        float var = sq * (1.f / PP) - mu * mu;
        float rs = rsqrtf(var + 1e-5f);
#pragma unroll
        for (int k = 0; k < 13; ++k) {
            int q = lane + 32 * k;
            if (q < PP) {
                float x = Cs[r * AH_STRIDE + q];
                Cs[r * AH_STRIDE + q] = (x - mu) * rs * smf[P_PG + q] + smf[P_PB2 + q];
            }
        }
    }
    __syncthreads();

    // ---- 5x5 circular conv + 0.1*sigmoid + transposed write ----
    int b = s0 >> 12;
    int sw0 = s0 & (SEQ - 1);
    float kreg[25];
#pragma unroll
    for (int d = 0; d < 25; ++d) kreg[d] = smf[P_KS + d];
    float cc0 = smf[P_KS + 25];

    for (int item = tid; item < 800; item += TB) {
        int r8 = (item & 7) * 8;
        int pgi = item >> 3;
        int ii = pgi / 5, jj0 = (pgi % 5) * 4;
        int wy[5], wx[8];
#pragma unroll
        for (int dy = 0; dy < 5; ++dy) wy[dy] = ((ii + dy - 2 + 20) % 20) * 20;
#pragma unroll
        for (int dx = 0; dx < 8; ++dx) wx[dx] = (jj0 + dx - 2 + 20) % 20;

        float o[4][8];
#pragma unroll
        for (int rr = 0; rr < 8; ++rr) {
            const float* crow = Cs + (r8 + rr) * AH_STRIDE;
            float patch[5][8];
#pragma unroll
            for (int dy = 0; dy < 5; ++dy)
#pragma unroll
                for (int dx = 0; dx < 8; ++dx)
                    patch[dy][dx] = crow[wy[dy] + wx[dx]];
#pragma unroll
            for (int t = 0; t < 4; ++t) {
                float a = cc0;
#pragma unroll
                for (int du = 0; du < 5; ++du)
#pragma unroll
                    for (int dv = 0; dv < 5; ++dv)
                        a += kreg[du * 5 + dv] * patch[du][t + dv];
                o[t][rr] = 0.1f / (1.f + __expf(-a));
            }
        }
#pragma unroll
        for (int t = 0; t < 4; ++t) {
            int p = ii * 20 + jj0 + t;
            float* obase = out + ((size_t)(b * PP + p)) * SEQ + sw0 + r8;
            *(float4*)(obase)     = make_float4(o[t][0], o[t][1], o[t][2], o[t][3]);
            *(float4*)(obase + 4) = make_float4(o[t][4], o[t][5], o[t][6], o[t][7]);
        }
    }
}

// ---------------- persistent selection: 2 gbars per iteration ---------------
__device__ __forceinline__ void gbar(unsigned& target)
{
    __syncthreads();
    __threadfence();
    if (threadIdx.x == 0) {
        atomicAdd(&g_bar, 1u);
        while (*(volatile unsigned*)&g_bar < target) { }
    }
    __syncthreads();
    __threadfence();
}

__global__ void __launch_bounds__(256) select_persistent(float* __restrict__ out)
{
    int b = blockIdx.x & 7;        // batch
    int g = blockIdx.x >> 3;       // 0..31 within batch
    int tid = threadIdx.x, lane = tid & 31, wid = tid >> 5;
    unsigned target = 0;
    int done_b = 0;
    __shared__ float ws[8];
    __shared__ float wvv[8];
    __shared__ int   wii[8];
    __shared__ float pw[4];
    __shared__ int   s_done, s_brk, s_pid;

    // ---- init slices ----
    if (g < 16) {
        int s = g * 256 + tid;
        float m = g_m[b * SEQ + s];
        g_res[b * SEQ + s] = 1.f;
        g_v2[b * SEQ + s] = m * m;
    } else if (g == 16 || g == 17) {
        int p = (g - 16) * 256 + tid;
        if (p < PP) g_sel[b * PP + p] = 0;
    } else if (g == 18 && tid == 0) {
        g_done[b] = 0;
    }
    target += NBLK; gbar(target);

    for (int it = 0; it < ITERS; ++it) {
        // ---- done-check from previous iteration's partials (per block) ----
        if (!done_b && it > 0) {
            if (tid == 0) {
                float t = 0.f;
#pragma unroll
                for (int i = 0; i < 32; ++i) t += g_part[b * 32 + i];
                s_done = (t * (1.f / SEQ) < 0.05f) ? 1 : 0;
            }
            __syncthreads();
            if (s_done) {
                done_b = 1;
                if (g == 0 && tid == 0) g_done[b] = 1;
            }
            __syncthreads();
        }

        // ---- activity phase ----
        if (!done_b) {
            const float4* vv = (const float4*)(g_v2 + (size_t)b * SEQ);
            for (int p = g; p < PP; p += 32) {
                if (g_sel[b * PP + p]) {
                    if (tid == 0) g_act[b * PP + p] = -1.f;
                    continue;
                }
                const float4* wp = (const float4*)(out + ((size_t)(b * PP + p)) * SEQ);
                float a = 0.f;
#pragma unroll
                for (int j = 0; j < 4; ++j) {
                    int k = tid + 256 * j;
                    float4 x = wp[k]; float4 y = vv[k];
                    a += x.x * x.x * y.x + x.y * x.y * y.y
                       + x.z * x.z * y.z + x.w * x.w * y.w;
                }
                for (int o = 16; o; o >>= 1) a += __shfl_xor_sync(~0u, a, o);
                if (lane == 0) ws[wid] = a;
                __syncthreads();
                if (tid == 0) {
                    float t = 0.f;
#pragma unroll
                    for (int i = 0; i < 8; ++i) t += ws[i];
                    g_act[b * PP + p] = t;
                }
                __syncthreads();
            }
        }
        target += NBLK; gbar(target);   // g_act + g_done visible

        // ---- all-done break ----
        if (tid == 0) {
            int ad = 1;
#pragma unroll
            for (int i = 0; i < 8; ++i) ad &= g_done[i];
            s_brk = ad;
        }
        __syncthreads();
        if (s_brk) break;

        // ---- redundant argmax (every block, identical result) + update -----
        if (!done_b) {
            float bv = -2.f; int bi = 0x7fffffff;
            for (int p = tid; p < PP; p += 256) {
                float v = g_act[b * PP + p];
                if (v > bv || (v == bv && p < bi)) { bv = v; bi = p; }
            }
            for (int o = 16; o; o >>= 1) {
                float ov = __shfl_xor_sync(~0u, bv, o);
                int   oi = __shfl_xor_sync(~0u, bi, o);
                if (ov > bv || (ov == bv && oi < bi)) { bv = ov; bi = oi; }
            }
            if (lane == 0) { wvv[wid] = bv; wii[wid] = bi; }
            __syncthreads();
            if (tid == 0) {
                float fv = -2.f; int fi = 0x7fffffff;
#pragma unroll
                for (int i = 0; i < 8; ++i)
                    if (wvv[i] > fv || (wvv[i] == fv && wii[i] < fi)) { fv = wvv[i]; fi = wii[i]; }
                s_pid = fi;
                g_sel[b * PP + fi] = 1;   // 32 blocks write same value
            }
            __syncthreads();
            int pid = s_pid;

            float part = 0.f;
            if (tid < 128) {
                int s = g * 128 + tid;
                const float* row = out + ((size_t)(b * PP + pid)) * SEQ;
                float r = g_res[b * SEQ + s] - row[s] * 10.f;
                r = fmaxf(r, 0.f);
                g_res[b * SEQ + s] = r;
                part = r;
                float v = r * g_m[b * SEQ + s];
                g_v2[b * SEQ + s] = v * v;
            }
            for (int o = 16; o; o >>= 1) part += __shfl_xor_sync(~0u, part, o);
            if (lane == 0 && wid < 4) pw[wid] = part;
            __syncthreads();
            if (tid == 0) g_part[b * 32 + g] = pw[0] + pw[1] + pw[2] + pw[3];
        }
        target += NBLK; gbar(target);   // res/v2/g_part/g_sel visible
    }

    // ---- rescale selected rows x10 ----
    for (int p = g; p < PP; p += 32) {
        if (g_sel[b * PP + p]) {
            float4* wp = (float4*)(out + ((size_t)(b * PP + p)) * SEQ);
#pragma unroll
            for (int j = 0; j < 4; ++j) {
                int k = tid + 256 * j;
                float4 x = wp[k];
                x.x *= 10.f; x.y *= 10.f; x.z *= 10.f; x.w *= 10.f;
                wp[k] = x;
            }
        }
    }
}

// ---------------- launch --------------------------------------------------
extern "C" void kernel_launch(void* const* d_in, const int* in_sizes, int n_in,
                              void* d_out, int out_size)
{
    const float* x0     = (const float*)d_in[0];
    const float* fc1_w  = (const float*)d_in[1];
    const float* fc1_b  = (const float*)d_in[2];
    const float* ln1_g  = (const float*)d_in[3];
    const float* ln1_b  = (const float*)d_in[4];
    const float* fc2_w  = (const float*)d_in[5];
    const float* fc2_b  = (const float*)d_in[6];
    const float* ln2_g  = (const float*)d_in[7];
    const float* ln2_b  = (const float*)d_in[8];
    const float* c1w    = (const float*)d_in[9];
    const float* c1b    = (const float*)d_in[10];
    const float* c2w    = (const float*)d_in[11];
    const float* c2b    = (const float*)d_in[12];
    float* out = (float*)d_out;

    cudaFuncSetAttribute(kernelB, cudaFuncAttributeMaxDynamicSharedMemorySize, SMEM_TOTAL);

    prep_kernel<<<701, 256>>>(fc2_w, c1w, c1b, c2w, c2b);
    kernelB<<<NSAMP / BM, TB, SMEM_TOTAL>>>(x0, fc1_w, fc1_b, ln1_g, ln1_b,
                                            fc2_b, ln2_g, ln2_b, out);
    select_persistent<<<NBLK, 256>>>(out);
}

// round 16
// speedup vs baseline: 2.1459x; 1.2495x over previous
#include <cuda_runtime.h>
#include <cuda_bf16.h>
#include <math.h>
#include <stdint.h>

// Problem constants
#define BATCH 8
#define SEQ   4096
#define PP    400           // 20x20
#define NSAMP (BATCH*SEQ)   // 32768
#define ITERS 12
#define NBLK  256           // persistent selection grid

// GEMM: M=32768 (64/CTA), N=448 (56 n8-tiles), K=400 (25 k16-steps)
#define NK16  25
#define NNT   56
#define TB    512           // kernelB threads (16 warps)

typedef unsigned long long u64;

// ---------------- scratch (static __device__, no allocations) ----------------
__device__ unsigned g_Bfrag[NK16 * NNT * 2 * 64];  // [k16][nt][plane][lane][2] u32
__device__ float  g_m[NSAMP];
__device__ float  g_keff[25];
__device__ float  g_c;
__device__ float  g_act[BATCH * PP];
__device__ int    g_sel[BATCH * PP];
__device__ int    g_done[BATCH];
__device__ float  g_part[BATCH * 32];
__device__ float  g_res[BATCH * SEQ];
__device__ float  g_v2[BATCH * SEQ];
__device__ unsigned g_bar;

// ---------------- helpers ----------------
__device__ __forceinline__ void bsplit(float lo, float hi, uint32_t& h, uint32_t& l)
{
    asm("cvt.rn.bf16x2.f32 %0,%1,%2;" : "=r"(h) : "f"(hi), "f"(lo));
    float hlo = __uint_as_float(h << 16);
    float hhi = __uint_as_float(h & 0xffff0000u);
    asm("cvt.rn.bf16x2.f32 %0,%1,%2;" : "=r"(l) : "f"(hi - hhi), "f"(lo - hlo));
}
__device__ __forceinline__ void mma16816(float* c, const uint32_t* a,
                                         uint32_t b0, uint32_t b1)
{
    asm volatile(
        "mma.sync.aligned.m16n8k16.row.col.f32.bf16.bf16.f32 "
        "{%0,%1,%2,%3},{%4,%5,%6,%7},{%8,%9},{%0,%1,%2,%3};"
        : "+f"(c[0]), "+f"(c[1]), "+f"(c[2]), "+f"(c[3])
        : "r"(a[0]), "r"(a[1]), "r"(a[2]), "r"(a[3]), "r"(b0), "r"(b1));
}

// ---------------- prep: B fragment planes + conv compose + barrier reset -----
__global__ void prep_kernel(const float* __restrict__ fc2_w,
                            const float* __restrict__ c1w, const float* __restrict__ c1b,
                            const float* __restrict__ c2w, const float* __restrict__ c2b)
{
    if (blockIdx.x < 700) {
        int e = blockIdx.x * 256 + threadIdx.x;   // [k16][nt][plane][lane][reg]
        int reg   = e & 1;
        int lane  = (e >> 1) & 31;
        int plane = (e >> 6) & 1;
        int r     = e >> 7;                        // 0..1399
        int nt  = r % NNT;
        int k16 = r / NNT;
        int g = lane >> 2, tg = lane & 3;
        int n  = nt * 8 + g;
        int kr = k16 * 16 + tg * 2 + reg * 8;
        float v0 = (n < PP) ? fc2_w[n * PP + kr] : 0.f;
        float v1 = (n < PP) ? fc2_w[n * PP + kr + 1] : 0.f;
        uint32_t h, l;
        bsplit(v0, v1, h, l);
        g_Bfrag[(((size_t)r * 2 + plane) * 32 + lane) * 2 + reg] = plane ? l : h;
        return;
    }
    // last block: keff compose + g_bar reset
    __shared__ float s1w[45], s1b[5], s2w[450], s2b[10], part[250];
    int t = threadIdx.x;
    if (t == 0) g_bar = 0u;
    if (t < 45)  s1w[t] = c1w[t];
    if (t < 5)   s1b[t] = c1b[t];
    for (int i = t; i < 450; i += 256) s2w[i] = c2w[i];
    if (t < 10)  s2b[t] = c2b[t];
    __syncthreads();
    if (t < 250) {
        int uv = t / 10, oc = t % 10;
        int u = uv / 5, v = uv % 5;
        float acc = 0.f;
        for (int ic = 0; ic < 5; ++ic)
#pragma unroll
            for (int ay = 0; ay < 3; ++ay) {
                int by = u - ay; if (by < 0 || by > 2) continue;
#pragma unroll
                for (int ax = 0; ax < 3; ++ax) {
                    int bx = v - ax; if (bx < 0 || bx > 2) continue;
                    acc += s2w[((oc * 5 + ic) * 3 + by) * 3 + bx] * s1w[(ic * 3 + ay) * 3 + ax];
                }
            }
        part[t] = acc;
    }
    __syncthreads();
    if (t < 25) {
        float acc = 0.f;
#pragma unroll
        for (int oc = 0; oc < 10; ++oc) acc += part[t * 10 + oc];
        g_keff[t] = acc * 0.1f;
    } else if (t == 25) {
        float acc = 0.f;
        for (int oc = 0; oc < 10; ++oc) {
            float t2 = s2b[oc];
            for (int ic = 0; ic < 5; ++ic) {
                float sw = 0.f;
#pragma unroll
                for (int bb = 0; bb < 9; ++bb) sw += s2w[(oc * 5 + ic) * 9 + bb];
                t2 += s1b[ic] * sw;
            }
            acc += t2;
        }
        g_c = acc * 0.1f;
    }
}

// ---- kernel B: 16 warps; fc1+ln1 + mma.sync bf16-split + ln2 + conv --------
#define BM 64
#define AH_STRIDE 405          // ODD: r8-group stride 8*405 % 32 = 8 -> 2-way max
#define REGION (BM * AH_STRIDE)
#define P_FW   (REGION)
#define P_FB   (P_FW + 1200)
#define P_L1G  (P_FB + PP)
#define P_L1B  (P_L1G + PP)
#define P_PB   (P_L1B + PP)
#define P_PG   (P_PB + PP)
#define P_PB2  (P_PG + PP)
#define P_KS   (P_PB2 + PP)
#define SMEM_TOTAL ((P_KS + 32) * 4)

__global__ void __launch_bounds__(TB, 1) kernelB(
    const float* __restrict__ x0,
    const float* __restrict__ fc1_w, const float* __restrict__ fc1_b,
    const float* __restrict__ ln1_g, const float* __restrict__ ln1_b,
    const float* __restrict__ fc2_b, const float* __restrict__ ln2_g,
    const float* __restrict__ ln2_b, float* __restrict__ out)
{
    extern __shared__ float smf[];
    float* Ah = smf;

    int tid = threadIdx.x, lane = tid & 31, wid = tid >> 5;   // 16 warps
    int s0 = blockIdx.x * BM;

    for (int i = tid; i < 1200; i += TB) smf[P_FW + i] = fc1_w[i];
    for (int i = tid; i < PP; i += TB) {
        smf[P_FB + i] = fc1_b[i]; smf[P_L1G + i] = ln1_g[i]; smf[P_L1B + i] = ln1_b[i];
        smf[P_PB + i] = fc2_b[i]; smf[P_PG + i] = ln2_g[i]; smf[P_PB2 + i] = ln2_b[i];
    }
    if (tid < 26) smf[P_KS + tid] = (tid < 25) ? g_keff[tid] : g_c;
    __syncthreads();

    // ---- fused fc1 + relu + ln1 into Ah (one warp per sample, 4 rounds) ----
    for (int r = wid; r < BM; r += 16) {
        int ss = s0 + r;
        const float* xp = x0 + (size_t)ss * 3;
        float xa = xp[0], xb = xp[1], xc = xp[2];
        if (lane == 0) g_m[ss] = (xa + xb + xc) * (1.f / 3.f);
        float v[13];
        float sum = 0.f, sq = 0.f;
#pragma unroll
        for (int k = 0; k < 13; ++k) {
            int q = lane + 32 * k;
            float h = 0.f;
            if (q < PP) {
                h = fmaxf(xa * smf[P_FW + q * 3] + xb * smf[P_FW + q * 3 + 1]
                        + xc * smf[P_FW + q * 3 + 2] + smf[P_FB + q], 0.f);
            }
            v[k] = h; sum += h; sq += h * h;
        }
        for (int o = 16; o; o >>= 1) {
            sum += __shfl_xor_sync(~0u, sum, o);
            sq  += __shfl_xor_sync(~0u, sq, o);
        }
        float mu = sum * (1.f / PP);
        float var = sq * (1.f / PP) - mu * mu;
        float rs = rsqrtf(var + 1e-5f);
#pragma unroll
        for (int k = 0; k < 13; ++k) {
            int q = lane + 32 * k;
            if (q < PP) Ah[r * AH_STRIDE + q] = (v[k] - mu) * rs * smf[P_L1G + q] + smf[P_L1B + q];
        }
    }
    __syncthreads();

    // ---- mma.sync bf16-split mainloop ----
    // warp = (mhalf, ng): 2 m16-blocks x 7 n8-tiles
    int mhalf = wid >> 3, ng = wid & 7;
    int g = lane >> 2, tg = lane & 3;
    float acc[2][7][4];
#pragma unroll
    for (int mi = 0; mi < 2; ++mi)
#pragma unroll
        for (int j = 0; j < 7; ++j)
#pragma unroll
            for (int i = 0; i < 4; ++i) acc[mi][j][i] = 0.f;

    const u64* bfr = (const u64*)g_Bfrag;

    for (int k16 = 0; k16 < NK16; ++k16) {
        int kb = k16 * 16;
        uint32_t aH[2][4], aL[2][4];
#pragma unroll
        for (int mi = 0; mi < 2; ++mi) {
            int mb = mhalf * 2 + mi;
            const float* b0p = Ah + (16 * mb + g) * AH_STRIDE + 2 * tg + kb;
            const float* b1p = Ah + (16 * mb + 8 + g) * AH_STRIDE + 2 * tg + kb;
            // scalar loads (odd stride -> float2 would be misaligned)
            bsplit(b0p[0], b0p[1], aH[mi][0], aL[mi][0]);
            bsplit(b1p[0], b1p[1], aH[mi][1], aL[mi][1]);
            bsplit(b0p[8], b0p[9], aH[mi][2], aL[mi][2]);
            bsplit(b1p[8], b1p[9], aH[mi][3], aL[mi][3]);
        }

        size_t base = ((size_t)(k16 * NNT + ng * 7)) * 64 + lane;
#pragma unroll
        for (int j = 0; j < 7; ++j) {
            u64 w0 = bfr[base + (size_t)j * 64];
            u64 w1 = bfr[base + (size_t)j * 64 + 32];
            uint32_t bH0 = (uint32_t)w0, bH1 = (uint32_t)(w0 >> 32);
            uint32_t bL0 = (uint32_t)w1, bL1 = (uint32_t)(w1 >> 32);
#pragma unroll
            for (int mi = 0; mi < 2; ++mi) {
                mma16816(acc[mi][j], aH[mi], bH0, bH1);
                mma16816(acc[mi][j], aH[mi], bL0, bL1);
                mma16816(acc[mi][j], aL[mi], bH0, bH1);
            }
        }
    }
    __syncthreads();

    // ---- bias + relu -> Cs (overlay Ah) ----
    float* Cs = Ah;
#pragma unroll
    for (int mi = 0; mi < 2; ++mi) {
        int mb = mhalf * 2 + mi;
        int rowa = (16 * mb + g) * AH_STRIDE;
        int rowb = (16 * mb + 8 + g) * AH_STRIDE;
#pragma unroll
        for (int j = 0; j < 7; ++j) {
            int q0 = (ng * 7 + j) * 8 + 2 * tg;
            if (q0 < PP) {
                Cs[rowa + q0] = fmaxf(acc[mi][j][0] + smf[P_PB + q0], 0.f);
                Cs[rowb + q0] = fmaxf(acc[mi][j][2] + smf[P_PB + q0], 0.f);
            }
            if (q0 + 1 < PP) {
                Cs[rowa + q0 + 1] = fmaxf(acc[mi][j][1] + smf[P_PB + q0 + 1], 0.f);
                Cs[rowb + q0 + 1] = fmaxf(acc[mi][j][3] + smf[P_PB + q0 + 1], 0.f);
            }
        }
    }
    __syncthreads();

    // ---- LN2 per sample row (16 warps x 4 rows) ----
    for (int r = wid * 4; r < wid * 4 + 4; ++r) {
        float sum = 0.f, sq = 0.f;
#pragma unroll
        for (int k = 0; k < 13; ++k) {
            int q = lane + 32 * k;
            if (q < PP) { float x = Cs[r * AH_STRIDE + q]; sum += x; sq += x * x; }
        }
        for (int o = 16; o; o >>= 1) {
            sum += __shfl_xor_sync(~0u, sum, o);
            sq  += __shfl_xor_sync(~0u, sq, o);
        }
        float mu = sum * (1.f / PP);
        float var = sq * (1.f / PP) - mu * mu;
        float rs = rsqrtf(var + 1e-5f);
#pragma unroll
        for (int k = 0; k < 13; ++k) {
            int q = lane + 32 * k;
            if (q < PP) {
                float x = Cs[r * AH_STRIDE + q];
                Cs[r * AH_STRIDE + q] = (x - mu) * rs * smf[P_PG + q] + smf[P_PB2 + q];
            }
        }
    }
    __syncthreads();

    // ---- 5x5 circular conv + 0.1*sigmoid + transposed write ----
    int b = s0 >> 12;
    int sw0 = s0 & (SEQ - 1);
    float kreg[25];
#pragma unroll
    for (int d = 0; d < 25; ++d) kreg[d] = smf[P_KS + d];
    float cc0 = smf[P_KS + 25];

    for (int item = tid; item < 800; item += TB) {
        int r8 = (item & 7) * 8;
        int pgi = item >> 3;
        int ii = pgi / 5, jj0 = (pgi % 5) * 4;
        int wy[5], wx[8];
#pragma unroll
        for (int dy = 0; dy < 5; ++dy) wy[dy] = ((ii + dy - 2 + 20) % 20) * 20;
#pragma unroll
        for (int dx = 0; dx < 8; ++dx) wx[dx] = (jj0 + dx - 2 + 20) % 20;

        float o[4][8];
#pragma unroll
        for (int rr = 0; rr < 8; ++rr) {
            const float* crow = Cs + (r8 + rr) * AH_STRIDE;
            float patch[5][8];
#pragma unroll
            for (int dy = 0; dy < 5; ++dy)
#pragma unroll
                for (int dx = 0; dx < 8; ++dx)
                    patch[dy][dx] = crow[wy[dy] + wx[dx]];
#pragma unroll
            for (int t = 0; t < 4; ++t) {
                float a = cc0;
#pragma unroll
                for (int du = 0; du < 5; ++du)
#pragma unroll
                    for (int dv = 0; dv < 5; ++dv)
                        a += kreg[du * 5 + dv] * patch[du][t + dv];
                o[t][rr] = 0.1f / (1.f + __expf(-a));
            }
        }
#pragma unroll
        for (int t = 0; t < 4; ++t) {
            int p = ii * 20 + jj0 + t;
            float* obase = out + ((size_t)(b * PP + p)) * SEQ + sw0 + r8;
            *(float4*)(obase)     = make_float4(o[t][0], o[t][1], o[t][2], o[t][3]);
            *(float4*)(obase + 4) = make_float4(o[t][4], o[t][5], o[t][6], o[t][7]);
        }
    }
}

// ---------------- persistent selection: 2 gbars per iteration ---------------
__device__ __forceinline__ void gbar(unsigned& target)
{
    __syncthreads();
    __threadfence();
    if (threadIdx.x == 0) {
        atomicAdd(&g_bar, 1u);
        while (*(volatile unsigned*)&g_bar < target) { }
    }
    __syncthreads();
    __threadfence();
}

__global__ void __launch_bounds__(256) select_persistent(float* __restrict__ out)
{
    int b = blockIdx.x & 7;        // batch
    int g = blockIdx.x >> 3;       // 0..31 within batch
    int tid = threadIdx.x, lane = tid & 31, wid = tid >> 5;
    unsigned target = 0;
    int done_b = 0;
    __shared__ float ws[8];
    __shared__ float wvv[8];
    __shared__ int   wii[8];
    __shared__ float pw[4];
    __shared__ int   s_done, s_brk, s_pid;

    // ---- init slices ----
    if (g < 16) {
        int s = g * 256 + tid;
        float m = g_m[b * SEQ + s];
        g_res[b * SEQ + s] = 1.f;
        g_v2[b * SEQ + s] = m * m;
    } else if (g == 16 || g == 17) {
        int p = (g - 16) * 256 + tid;
        if (p < PP) g_sel[b * PP + p] = 0;
    } else if (g == 18 && tid == 0) {
        g_done[b] = 0;
    }
    target += NBLK; gbar(target);

    for (int it = 0; it < ITERS; ++it) {
        // ---- done-check from previous iteration's partials (per block) ----
        if (!done_b && it > 0) {
            if (tid == 0) {
                float t = 0.f;
#pragma unroll
                for (int i = 0; i < 32; ++i) t += g_part[b * 32 + i];
                s_done = (t * (1.f / SEQ) < 0.05f) ? 1 : 0;
            }
            __syncthreads();
            if (s_done) {
                done_b = 1;
                if (g == 0 && tid == 0) g_done[b] = 1;
            }
            __syncthreads();
        }

        // ---- activity phase ----
        if (!done_b) {
            const float4* vv = (const float4*)(g_v2 + (size_t)b * SEQ);
            for (int p = g; p < PP; p += 32) {
                if (g_sel[b * PP + p]) {
                    if (tid == 0) g_act[b * PP + p] = -1.f;
                    continue;
                }
                const float4* wp = (const float4*)(out + ((size_t)(b * PP + p)) * SEQ);
                float a = 0.f;
#pragma unroll
                for (int j = 0; j < 4; ++j) {
                    int k = tid + 256 * j;
                    float4 x = wp[k]; float4 y = vv[k];
                    a += x.x * x.x * y.x + x.y * x.y * y.y
                       + x.z * x.z * y.z + x.w * x.w * y.w;
                }
                for (int o = 16; o; o >>= 1) a += __shfl_xor_sync(~0u, a, o);
                if (lane == 0) ws[wid] = a;
                __syncthreads();
                if (tid == 0) {
                    float t = 0.f;
#pragma unroll
                    for (int i = 0; i < 8; ++i) t += ws[i];
                    g_act[b * PP + p] = t;
                }
                __syncthreads();
            }
        }
        target += NBLK; gbar(target);   // g_act + g_done visible

        // ---- all-done break ----
        if (tid == 0) {
            int ad = 1;
#pragma unroll
            for (int i = 0; i < 8; ++i) ad &= g_done[i];
            s_brk = ad;
        }
        __syncthreads();
        if (s_brk) break;

        // ---- redundant argmax (every block, identical result) + update -----
        if (!done_b) {
            float bv = -2.f; int bi = 0x7fffffff;
            for (int p = tid; p < PP; p += 256) {
                float v = g_act[b * PP + p];
                if (v > bv || (v == bv && p < bi)) { bv = v; bi = p; }
            }
            for (int o = 16; o; o >>= 1) {
                float ov = __shfl_xor_sync(~0u, bv, o);
                int   oi = __shfl_xor_sync(~0u, bi, o);
                if (ov > bv || (ov == bv && oi < bi)) { bv = ov; bi = oi; }
            }
            if (lane == 0) { wvv[wid] = bv; wii[wid] = bi; }
            __syncthreads();
            if (tid == 0) {
                float fv = -2.f; int fi = 0x7fffffff;
#pragma unroll
                for (int i = 0; i < 8; ++i)
                    if (wvv[i] > fv || (wvv[i] == fv && wii[i] < fi)) { fv = wvv[i]; fi = wii[i]; }
                s_pid = fi;
                g_sel[b * PP + fi] = 1;   // 32 blocks write same value
            }
            __syncthreads();
            int pid = s_pid;

            float part = 0.f;
            if (tid < 128) {
                int s = g * 128 + tid;
                const float* row = out + ((size_t)(b * PP + pid)) * SEQ;
                float r = g_res[b * SEQ + s] - row[s] * 10.f;
                r = fmaxf(r, 0.f);
                g_res[b * SEQ + s] = r;
                part = r;
                float v = r * g_m[b * SEQ + s];
                g_v2[b * SEQ + s] = v * v;
            }
            for (int o = 16; o; o >>= 1) part += __shfl_xor_sync(~0u, part, o);
            if (lane == 0 && wid < 4) pw[wid] = part;
            __syncthreads();
            if (tid == 0) g_part[b * 32 + g] = pw[0] + pw[1] + pw[2] + pw[3];
        }
        target += NBLK; gbar(target);   // res/v2/g_part/g_sel visible
    }

    // ---- rescale selected rows x10 ----
    for (int p = g; p < PP; p += 32) {
        if (g_sel[b * PP + p]) {
            float4* wp = (float4*)(out + ((size_t)(b * PP + p)) * SEQ);
#pragma unroll
            for (int j = 0; j < 4; ++j) {
                int k = tid + 256 * j;
                float4 x = wp[k];
                x.x *= 10.f; x.y *= 10.f; x.z *= 10.f; x.w *= 10.f;
                wp[k] = x;
            }
        }
    }
}

// ---------------- launch --------------------------------------------------
extern "C" void kernel_launch(void* const* d_in, const int* in_sizes, int n_in,
                              void* d_out, int out_size)
{
    const float* x0     = (const float*)d_in[0];
    const float* fc1_w  = (const float*)d_in[1];
    const float* fc1_b  = (const float*)d_in[2];
    const float* ln1_g  = (const float*)d_in[3];
    const float* ln1_b  = (const float*)d_in[4];
    const float* fc2_w  = (const float*)d_in[5];
    const float* fc2_b  = (const float*)d_in[6];
    const float* ln2_g  = (const float*)d_in[7];
    const float* ln2_b  = (const float*)d_in[8];
    const float* c1w    = (const float*)d_in[9];
    const float* c1b    = (const float*)d_in[10];
    const float* c2w    = (const float*)d_in[11];
    const float* c2b    = (const float*)d_in[12];
    float* out = (float*)d_out;

    cudaFuncSetAttribute(kernelB, cudaFuncAttributeMaxDynamicSharedMemorySize, SMEM_TOTAL);

    prep_kernel<<<701, 256>>>(fc2_w, c1w, c1b, c2w, c2b);
    kernelB<<<NSAMP / BM, TB, SMEM_TOTAL>>>(x0, fc1_w, fc1_b, ln1_g, ln1_b,
                                            fc2_b, ln2_g, ln2_b, out);
    select_persistent<<<NBLK, 256>>>(out);
}

// round 17
// speedup vs baseline: 2.1733x; 1.0128x over previous
#include <cuda_runtime.h>
#include <cuda_bf16.h>
#include <math.h>
#include <stdint.h>

// Problem constants
#define BATCH 8
#define SEQ   4096
#define PP    400           // 20x20
#define NSAMP (BATCH*SEQ)   // 32768
#define ITERS 12
#define NBLK  256           // persistent selection grid (32 blocks per batch)

// GEMM: M=32768 (64/CTA), N=448 (56 n8-tiles), K=400 (25 k16-steps)
#define NK16  25
#define NNT   56
#define TB    512           // kernelB threads (16 warps)

typedef unsigned long long u64;

// ---------------- scratch (static __device__, no allocations) ----------------
__device__ unsigned g_Bfrag[NK16 * NNT * 2 * 64];  // [k16][nt][plane][lane][2] u32
__device__ float  g_m[NSAMP];
__device__ float  g_keff[25];
__device__ float  g_c;
__device__ float  g_act[BATCH * PP];
__device__ int    g_sel[BATCH * PP];
__device__ float  g_part[BATCH * 32];
__device__ float  g_res[BATCH * SEQ];
__device__ float  g_v2[BATCH * SEQ];
__device__ unsigned g_barb[BATCH];     // per-batch barrier counters

// ---------------- helpers ----------------
__device__ __forceinline__ void bsplit(float lo, float hi, uint32_t& h, uint32_t& l)
{
    asm("cvt.rn.bf16x2.f32 %0,%1,%2;" : "=r"(h) : "f"(hi), "f"(lo));
    float hlo = __uint_as_float(h << 16);
    float hhi = __uint_as_float(h & 0xffff0000u);
    asm("cvt.rn.bf16x2.f32 %0,%1,%2;" : "=r"(l) : "f"(hi - hhi), "f"(lo - hlo));
}
__device__ __forceinline__ void mma16816(float* c, const uint32_t* a,
                                         uint32_t b0, uint32_t b1)
{
    asm volatile(
        "mma.sync.aligned.m16n8k16.row.col.f32.bf16.bf16.f32 "
        "{%0,%1,%2,%3},{%4,%5,%6,%7},{%8,%9},{%0,%1,%2,%3};"
        : "+f"(c[0]), "+f"(c[1]), "+f"(c[2]), "+f"(c[3])
        : "r"(a[0]), "r"(a[1]), "r"(a[2]), "r"(a[3]), "r"(b0), "r"(b1));
}

// ---------------- prep: B fragment planes + conv compose + barrier reset -----
__global__ void prep_kernel(const float* __restrict__ fc2_w,
                            const float* __restrict__ c1w, const float* __restrict__ c1b,
                            const float* __restrict__ c2w, const float* __restrict__ c2b)
{
    if (blockIdx.x < 700) {
        int e = blockIdx.x * 256 + threadIdx.x;   // [k16][nt][plane][lane][reg]
        int reg   = e & 1;
        int lane  = (e >> 1) & 31;
        int plane = (e >> 6) & 1;
        int r     = e >> 7;                        // 0..1399
        int nt  = r % NNT;
        int k16 = r / NNT;
        int g = lane >> 2, tg = lane & 3;
        int n  = nt * 8 + g;
        int kr = k16 * 16 + tg * 2 + reg * 8;
        float v0 = (n < PP) ? fc2_w[n * PP + kr] : 0.f;
        float v1 = (n < PP) ? fc2_w[n * PP + kr + 1] : 0.f;
        uint32_t h, l;
        bsplit(v0, v1, h, l);
        g_Bfrag[(((size_t)r * 2 + plane) * 32 + lane) * 2 + reg] = plane ? l : h;
        return;
    }
    // last block: keff compose + barrier resets
    __shared__ float s1w[45], s1b[5], s2w[450], s2b[10], part[250];
    int t = threadIdx.x;
    if (t < BATCH) g_barb[t] = 0u;
    if (t < 45)  s1w[t] = c1w[t];
    if (t < 5)   s1b[t] = c1b[t];
    for (int i = t; i < 450; i += 256) s2w[i] = c2w[i];
    if (t < 10)  s2b[t] = c2b[t];
    __syncthreads();
    if (t < 250) {
        int uv = t / 10, oc = t % 10;
        int u = uv / 5, v = uv % 5;
        float acc = 0.f;
        for (int ic = 0; ic < 5; ++ic)
#pragma unroll
            for (int ay = 0; ay < 3; ++ay) {
                int by = u - ay; if (by < 0 || by > 2) continue;
#pragma unroll
                for (int ax = 0; ax < 3; ++ax) {
                    int bx = v - ax; if (bx < 0 || bx > 2) continue;
                    acc += s2w[((oc * 5 + ic) * 3 + by) * 3 + bx] * s1w[(ic * 3 + ay) * 3 + ax];
                }
            }
        part[t] = acc;
    }
    __syncthreads();
    if (t < 25) {
        float acc = 0.f;
#pragma unroll
        for (int oc = 0; oc < 10; ++oc) acc += part[t * 10 + oc];
        g_keff[t] = acc * 0.1f;
    } else if (t == 25) {
        float acc = 0.f;
        for (int oc = 0; oc < 10; ++oc) {
            float t2 = s2b[oc];
            for (int ic = 0; ic < 5; ++ic) {
                float sw = 0.f;
#pragma unroll
                for (int bb = 0; bb < 9; ++bb) sw += s2w[(oc * 5 + ic) * 9 + bb];
                t2 += s1b[ic] * sw;
            }
            acc += t2;
        }
        g_c = acc * 0.1f;
    }
}

// ---- kernel B: 16 warps; fc1+ln1 + mma.sync bf16-split + ln2 + conv --------
#define BM 64
#define AH_STRIDE 405          // ODD: r8-group stride 8*405 % 32 = 8 -> 2-way max
#define REGION (BM * AH_STRIDE)
#define P_FW   (REGION)
#define P_FB   (P_FW + 1200)
#define P_L1G  (P_FB + PP)
#define P_L1B  (P_L1G + PP)
#define P_PB   (P_L1B + PP)
#define P_PG   (P_PB + PP)
#define P_PB2  (P_PG + PP)
#define P_KS   (P_PB2 + PP)
#define SMEM_TOTAL ((P_KS + 32) * 4)

__global__ void __launch_bounds__(TB, 1) kernelB(
    const float* __restrict__ x0,
    const float* __restrict__ fc1_w, const float* __restrict__ fc1_b,
    const float* __restrict__ ln1_g, const float* __restrict__ ln1_b,
    const float* __restrict__ fc2_b, const float* __restrict__ ln2_g,
    const float* __restrict__ ln2_b, float* __restrict__ out)
{
    extern __shared__ float smf[];
    float* Ah = smf;

    int tid = threadIdx.x, lane = tid & 31, wid = tid >> 5;   // 16 warps
    int s0 = blockIdx.x * BM;

    for (int i = tid; i < 1200; i += TB) smf[P_FW + i] = fc1_w[i];
    for (int i = tid; i < PP; i += TB) {
        smf[P_FB + i] = fc1_b[i]; smf[P_L1G + i] = ln1_g[i]; smf[P_L1B + i] = ln1_b[i];
        smf[P_PB + i] = fc2_b[i]; smf[P_PG + i] = ln2_g[i]; smf[P_PB2 + i] = ln2_b[i];
    }
    if (tid < 26) smf[P_KS + tid] = (tid < 25) ? g_keff[tid] : g_c;
    __syncthreads();

    // ---- fused fc1 + relu + ln1 into Ah (one warp per sample, 4 rounds) ----
    for (int r = wid; r < BM; r += 16) {
        int ss = s0 + r;
        const float* xp = x0 + (size_t)ss * 3;
        float xa = xp[0], xb = xp[1], xc = xp[2];
        if (lane == 0) g_m[ss] = (xa + xb + xc) * (1.f / 3.f);
        float v[13];
        float sum = 0.f, sq = 0.f;
#pragma unroll
        for (int k = 0; k < 13; ++k) {
            int q = lane + 32 * k;
            float h = 0.f;
            if (q < PP) {
                h = fmaxf(xa * smf[P_FW + q * 3] + xb * smf[P_FW + q * 3 + 1]
                        + xc * smf[P_FW + q * 3 + 2] + smf[P_FB + q], 0.f);
            }
            v[k] = h; sum += h; sq += h * h;
        }
        for (int o = 16; o; o >>= 1) {
            sum += __shfl_xor_sync(~0u, sum, o);
            sq  += __shfl_xor_sync(~0u, sq, o);
        }
        float mu = sum * (1.f / PP);
        float var = sq * (1.f / PP) - mu * mu;
        float rs = rsqrtf(var + 1e-5f);
#pragma unroll
        for (int k = 0; k < 13; ++k) {
            int q = lane + 32 * k;
            if (q < PP) Ah[r * AH_STRIDE + q] = (v[k] - mu) * rs * smf[P_L1G + q] + smf[P_L1B + q];
        }
    }
    __syncthreads();

    // ---- mma.sync bf16-split mainloop ----
    int mhalf = wid >> 3, ng = wid & 7;
    int g = lane >> 2, tg = lane & 3;
    float acc[2][7][4];
#pragma unroll
    for (int mi = 0; mi < 2; ++mi)
#pragma unroll
        for (int j = 0; j < 7; ++j)
#pragma unroll
            for (int i = 0; i < 4; ++i) acc[mi][j][i] = 0.f;

    const u64* bfr = (const u64*)g_Bfrag;

    for (int k16 = 0; k16 < NK16; ++k16) {
        int kb = k16 * 16;
        uint32_t aH[2][4], aL[2][4];
#pragma unroll
        for (int mi = 0; mi < 2; ++mi) {
            int mb = mhalf * 2 + mi;
            const float* b0p = Ah + (16 * mb + g) * AH_STRIDE + 2 * tg + kb;
            const float* b1p = Ah + (16 * mb + 8 + g) * AH_STRIDE + 2 * tg + kb;
            bsplit(b0p[0], b0p[1], aH[mi][0], aL[mi][0]);
            bsplit(b1p[0], b1p[1], aH[mi][1], aL[mi][1]);
            bsplit(b0p[8], b0p[9], aH[mi][2], aL[mi][2]);
            bsplit(b1p[8], b1p[9], aH[mi][3], aL[mi][3]);
        }

        size_t base = ((size_t)(k16 * NNT + ng * 7)) * 64 + lane;
#pragma unroll
        for (int j = 0; j < 7; ++j) {
            u64 w0 = bfr[base + (size_t)j * 64];
            u64 w1 = bfr[base + (size_t)j * 64 + 32];
            uint32_t bH0 = (uint32_t)w0, bH1 = (uint32_t)(w0 >> 32);
            uint32_t bL0 = (uint32_t)w1, bL1 = (uint32_t)(w1 >> 32);
#pragma unroll
            for (int mi = 0; mi < 2; ++mi) {
                mma16816(acc[mi][j], aH[mi], bH0, bH1);
                mma16816(acc[mi][j], aH[mi], bL0, bL1);
                mma16816(acc[mi][j], aL[mi], bH0, bH1);
            }
        }
    }
    __syncthreads();

    // ---- bias + relu -> Cs (overlay Ah) ----
    float* Cs = Ah;
#pragma unroll
    for (int mi = 0; mi < 2; ++mi) {
        int mb = mhalf * 2 + mi;
        int rowa = (16 * mb + g) * AH_STRIDE;
        int rowb = (16 * mb + 8 + g) * AH_STRIDE;
#pragma unroll
        for (int j = 0; j < 7; ++j) {
            int q0 = (ng * 7 + j) * 8 + 2 * tg;
            if (q0 < PP) {
                Cs[rowa + q0] = fmaxf(acc[mi][j][0] + smf[P_PB + q0], 0.f);
                Cs[rowb + q0] = fmaxf(acc[mi][j][2] + smf[P_PB + q0], 0.f);
            }
            if (q0 + 1 < PP) {
                Cs[rowa + q0 + 1] = fmaxf(acc[mi][j][1] + smf[P_PB + q0 + 1], 0.f);
                Cs[rowb + q0 + 1] = fmaxf(acc[mi][j][3] + smf[P_PB + q0 + 1], 0.f);
            }
        }
    }
    __syncthreads();

    // ---- LN2 per sample row (16 warps x 4 rows) ----
    for (int r = wid * 4; r < wid * 4 + 4; ++r) {
        float sum = 0.f, sq = 0.f;
#pragma unroll
        for (int k = 0; k < 13; ++k) {
            int q = lane + 32 * k;
            if (q < PP) { float x = Cs[r * AH_STRIDE + q]; sum += x; sq += x * x; }
        }
        for (int o = 16; o; o >>= 1) {
            sum += __shfl_xor_sync(~0u, sum, o);
            sq  += __shfl_xor_sync(~0u, sq, o);
        }
        float mu = sum * (1.f / PP);
        float var = sq * (1.f / PP) - mu * mu;
        float rs = rsqrtf(var + 1e-5f);
#pragma unroll
        for (int k = 0; k < 13; ++k) {
            int q = lane + 32 * k;
            if (q < PP) {
                float x = Cs[r * AH_STRIDE + q];
                Cs[r * AH_STRIDE + q] = (x - mu) * rs * smf[P_PG + q] + smf[P_PB2 + q];
            }
        }
    }
    __syncthreads();

    // ---- 5x5 circular conv + 0.1*sigmoid + transposed write ----
    int b = s0 >> 12;
    int sw0 = s0 & (SEQ - 1);
    float kreg[25];
#pragma unroll
    for (int d = 0; d < 25; ++d) kreg[d] = smf[P_KS + d];
    float cc0 = smf[P_KS + 25];

    for (int item = tid; item < 800; item += TB) {
        int r8 = (item & 7) * 8;
        int pgi = item >> 3;
        int ii = pgi / 5, jj0 = (pgi % 5) * 4;
        int wy[5], wx[8];
#pragma unroll
        for (int dy = 0; dy < 5; ++dy) wy[dy] = ((ii + dy - 2 + 20) % 20) * 20;
#pragma unroll
        for (int dx = 0; dx < 8; ++dx) wx[dx] = (jj0 + dx - 2 + 20) % 20;

        float o[4][8];
#pragma unroll
        for (int rr = 0; rr < 8; ++rr) {
            const float* crow = Cs + (r8 + rr) * AH_STRIDE;
            float patch[5][8];
#pragma unroll
            for (int dy = 0; dy < 5; ++dy)
#pragma unroll
                for (int dx = 0; dx < 8; ++dx)
                    patch[dy][dx] = crow[wy[dy] + wx[dx]];
#pragma unroll
            for (int t = 0; t < 4; ++t) {
                float a = cc0;
#pragma unroll
                for (int du = 0; du < 5; ++du)
#pragma unroll
                    for (int dv = 0; dv < 5; ++dv)
                        a += kreg[du * 5 + dv] * patch[du][t + dv];
                o[t][rr] = 0.1f / (1.f + __expf(-a));
            }
        }
#pragma unroll
        for (int t = 0; t < 4; ++t) {
            int p = ii * 20 + jj0 + t;
            float* obase = out + ((size_t)(b * PP + p)) * SEQ + sw0 + r8;
            *(float4*)(obase)     = make_float4(o[t][0], o[t][1], o[t][2], o[t][3]);
            *(float4*)(obase + 4) = make_float4(o[t][4], o[t][5], o[t][6], o[t][7]);
        }
    }
}

// ---------------- persistent selection: per-batch barriers ------------------
__device__ __forceinline__ void gbarb(int b, unsigned& target)
{
    __syncthreads();
    __threadfence();
    if (threadIdx.x == 0) {
        atomicAdd(&g_barb[b], 1u);
        while (*(volatile unsigned*)&g_barb[b] < target) { }
    }
    __syncthreads();
    __threadfence();
}

__global__ void __launch_bounds__(256) select_persistent(float* __restrict__ out)
{
    int b = blockIdx.x & 7;        // batch
    int g = blockIdx.x >> 3;       // 0..31 within batch
    int tid = threadIdx.x, lane = tid & 31, wid = tid >> 5;
    unsigned target = 0;
    __shared__ float ws[8];
    __shared__ float wvv[8];
    __shared__ int   wii[8];
    __shared__ float pw[4];
    __shared__ int   s_done, s_pid;

    // ---- init slices (all within this batch) ----
    if (g < 16) {
        int s = g * 256 + tid;
        float m = g_m[b * SEQ + s];
        g_res[b * SEQ + s] = 1.f;
        g_v2[b * SEQ + s] = m * m;
    } else if (g == 16 || g == 17) {
        int p = (g - 16) * 256 + tid;
        if (p < PP) g_sel[b * PP + p] = 0;
    }
    target += 32; gbarb(b, target);

    for (int it = 0; it < ITERS; ++it) {
        // ---- activity phase ----
        {
            const float4* vv = (const float4*)(g_v2 + (size_t)b * SEQ);
            for (int p = g; p < PP; p += 32) {
                if (g_sel[b * PP + p]) {
                    if (tid == 0) g_act[b * PP + p] = -1.f;
                    continue;
                }
                const float4* wp = (const float4*)(out + ((size_t)(b * PP + p)) * SEQ);
                float a = 0.f;
#pragma unroll
                for (int j = 0; j < 4; ++j) {
                    int k = tid + 256 * j;
                    float4 x = wp[k]; float4 y = vv[k];
                    a += x.x * x.x * y.x + x.y * x.y * y.y
                       + x.z * x.z * y.z + x.w * x.w * y.w;
                }
                for (int o = 16; o; o >>= 1) a += __shfl_xor_sync(~0u, a, o);
                if (lane == 0) ws[wid] = a;
                __syncthreads();
                if (tid == 0) {
                    float t = 0.f;
#pragma unroll
                    for (int i = 0; i < 8; ++i) t += ws[i];
                    g_act[b * PP + p] = t;
                }
                __syncthreads();
            }
        }
        target += 32; gbarb(b, target);   // g_act visible

        // ---- redundant argmax (every block, identical result) + update -----
        {
            float bv = -2.f; int bi = 0x7fffffff;
            for (int p = tid; p < PP; p += 256) {
                float v = g_act[b * PP + p];
                if (v > bv || (v == bv && p < bi)) { bv = v; bi = p; }
            }
            for (int o = 16; o; o >>= 1) {
                float ov = __shfl_xor_sync(~0u, bv, o);
                int   oi = __shfl_xor_sync(~0u, bi, o);
                if (ov > bv || (ov == bv && oi < bi)) { bv = ov; bi = oi; }
            }
            if (lane == 0) { wvv[wid] = bv; wii[wid] = bi; }
            __syncthreads();
            if (tid == 0) {
                float fv = -2.f; int fi = 0x7fffffff;
#pragma unroll
                for (int i = 0; i < 8; ++i)
                    if (wvv[i] > fv || (wvv[i] == fv && wii[i] < fi)) { fv = wvv[i]; fi = wii[i]; }
                s_pid = fi;
                g_sel[b * PP + fi] = 1;   // 32 blocks write same value
            }
            __syncthreads();
            int pid = s_pid;

            float part = 0.f;
            if (tid < 128) {
                int s = g * 128 + tid;
                const float* row = out + ((size_t)(b * PP + pid)) * SEQ;
                float r = g_res[b * SEQ + s] - row[s] * 10.f;
                r = fmaxf(r, 0.f);
                g_res[b * SEQ + s] = r;
                part = r;
                float v = r * g_m[b * SEQ + s];
                g_v2[b * SEQ + s] = v * v;
            }
            for (int o = 16; o; o >>= 1) part += __shfl_xor_sync(~0u, part, o);
            if (lane == 0 && wid < 4) pw[wid] = part;
            __syncthreads();
            if (tid == 0) g_part[b * 32 + g] = pw[0] + pw[1] + pw[2] + pw[3];
        }
        target += 32; gbarb(b, target);   // res/v2/g_part/g_sel visible

        // ---- done-check (per block, deterministic fixed-order sum) ----
        if (tid == 0) {
            float t = 0.f;
#pragma unroll
            for (int i = 0; i < 32; ++i) t += g_part[b * 32 + i];
            s_done = (t * (1.f / SEQ) < 0.05f) ? 1 : 0;
        }
        __syncthreads();
        if (s_done) break;
    }

    // ---- rescale selected rows x10 (own batch only; after own barrier) ----
    for (int p = g; p < PP; p += 32) {
        if (g_sel[b * PP + p]) {
            float4* wp = (float4*)(out + ((size_t)(b * PP + p)) * SEQ);
#pragma unroll
            for (int j = 0; j < 4; ++j) {
                int k = tid + 256 * j;
                float4 x = wp[k];
                x.x *= 10.f; x.y *= 10.f; x.z *= 10.f; x.w *= 10.f;
                wp[k] = x;
            }
        }
    }
}

// ---------------- launch --------------------------------------------------
extern "C" void kernel_launch(void* const* d_in, const int* in_sizes, int n_in,
                              void* d_out, int out_size)
{
    const float* x0     = (const float*)d_in[0];
    const float* fc1_w  = (const float*)d_in[1];
    const float* fc1_b  = (const float*)d_in[2];
    const float* ln1_g  = (const float*)d_in[3];
    const float* ln1_b  = (const float*)d_in[4];
    const float* fc2_w  = (const float*)d_in[5];
    const float* fc2_b  = (const float*)d_in[6];
    const float* ln2_g  = (const float*)d_in[7];
    const float* ln2_b  = (const float*)d_in[8];
    const float* c1w    = (const float*)d_in[9];
    const float* c1b    = (const float*)d_in[10];
    const float* c2w    = (const float*)d_in[11];
    const float* c2b    = (const float*)d_in[12];
    float* out = (float*)d_out;

    cudaFuncSetAttribute(kernelB, cudaFuncAttributeMaxDynamicSharedMemorySize, SMEM_TOTAL);

    prep_kernel<<<701, 256>>>(fc2_w, c1w, c1b, c2w, c2b);
    kernelB<<<NSAMP / BM, TB, SMEM_TOTAL>>>(x0, fc1_w, fc1_b, ln1_g, ln1_b,
                                            fc2_b, ln2_g, ln2_b, out);
    select_persistent<<<NBLK, 256>>>(out);
}